// round 2
// baseline (speedup 1.0000x reference)
#include <cuda_runtime.h>
#include <math.h>

// Problem constants
#define NTOK 16384      // B*S
#define HDIM 1024
#define IDIM 2048
#define NEXP 8
#define NSLOT (2*NTOK)  // total (token, expert) slots

// ---------------- device scratch (static: no allocs allowed) ----------------
__device__ int   g_count[NEXP];
__device__ int   g_base[NEXP + 1];
__device__ int   g_perm[NEXP * NTOK];     // token id per (expert, pos)
__device__ int   g_tokexp[NSLOT];         // expert per (token, slot)
__device__ int   g_tokpos[NSLOT];         // pos within expert per (token, slot)
__device__ float g_tokw[NSLOT];           // combine weight per (token, slot)
__device__ float g_h[(size_t)NSLOT * IDIM];   // stage-1 output (silu(g)*u), 256MB
__device__ float g_y[(size_t)NSLOT * HDIM];   // stage-2 output, 128MB

// ---------------- tiny helpers ----------------
__global__ void zero_counts_kernel() {
    if (threadIdx.x < NEXP) g_count[threadIdx.x] = 0;
}

__global__ void scan_base_kernel() {
    int b = 0;
    g_base[0] = 0;
    #pragma unroll
    for (int e = 0; e < NEXP; e++) { b += g_count[e]; g_base[e + 1] = b; }
}

// ---------------- router: logits -> top2 -> renorm -> scatter ----------------
__global__ void router_kernel(const float* __restrict__ X,
                              const float* __restrict__ RW) {
    int gwarp = (blockIdx.x * blockDim.x + threadIdx.x) >> 5;
    int lane  = threadIdx.x & 31;
    if (gwarp >= NTOK) return;
    const float4* x4 = reinterpret_cast<const float4*>(X + (size_t)gwarp * HDIM);

    float l[NEXP];
    #pragma unroll
    for (int e = 0; e < NEXP; e++) {
        const float4* w4 = reinterpret_cast<const float4*>(RW + e * HDIM);
        float s = 0.f;
        #pragma unroll
        for (int i = 0; i < 8; i++) {
            float4 a = x4[lane + 32 * i];
            float4 b = w4[lane + 32 * i];
            s += a.x * b.x + a.y * b.y + a.z * b.z + a.w * b.w;
        }
        #pragma unroll
        for (int o = 16; o > 0; o >>= 1) s += __shfl_xor_sync(0xffffffffu, s, o);
        l[e] = s;
    }

    if (lane == 0) {
        // top-2 with first-occurrence tie-breaking (matches jax top_k)
        int e0 = 0; float l0 = l[0];
        #pragma unroll
        for (int e = 1; e < NEXP; e++) { if (l[e] > l0) { l0 = l[e]; e0 = e; } }
        int e1 = -1; float l1 = -1e30f;
        #pragma unroll
        for (int e = 0; e < NEXP; e++) {
            if (e != e0 && l[e] > l1) { l1 = l[e]; e1 = e; }
        }
        // renormalized top-2 softmax weights (== softmax-then-renorm)
        float d  = __expf(l1 - l0);          // <= 1
        float w0 = 1.f / (1.f + d);
        float w1 = 1.f - w0;

        int n = gwarp;
        int p0 = atomicAdd(&g_count[e0], 1);
        g_perm[e0 * NTOK + p0] = n;
        g_tokexp[2 * n] = e0; g_tokpos[2 * n] = p0; g_tokw[2 * n] = w0;
        int p1 = atomicAdd(&g_count[e1], 1);
        g_perm[e1 * NTOK + p1] = n;
        g_tokexp[2 * n + 1] = e1; g_tokpos[2 * n + 1] = p1; g_tokw[2 * n + 1] = w1;
    }
}

// ---------------- stage 1: h = silu(X @ gateT) * (X @ upT), gathered rows ----
// Tile: BM=128 rows, BN=64 I-cols, BK=16. 256 threads, 8x4 microtile, dual acc.
#define BM1 128
#define BN1 64
#define BK  16

__global__ __launch_bounds__(256, 2)
void gemm1_kernel(const float* __restrict__ X,
                  const float* __restrict__ GW,
                  const float* __restrict__ UW) {
    int e    = blockIdx.z;
    int M    = g_count[e];
    int row0 = blockIdx.y * BM1;
    if (row0 >= M) return;
    int n0   = blockIdx.x * BN1;
    int base = g_base[e];

    __shared__ float As [BK][BM1 + 4];
    __shared__ float Bgs[BK][BN1 + 4];
    __shared__ float Bus[BK][BN1 + 4];

    int tid = threadIdx.x;
    int tx  = tid & 15;   // col group: cols n0 + tx*4 .. +3
    int ty  = tid >> 4;   // row group: rows row0 + ty*8 .. +7

    // A-load mapping: 512 float4 chunks (128 rows x 4 f4), 2 per thread
    const float4* arow[2];
    int akq[2];
    #pragma unroll
    for (int i = 0; i < 2; i++) {
        int c = tid + i * 256;
        int r = c >> 2;
        akq[i] = c & 3;
        int rr = row0 + r; if (rr > M - 1) rr = M - 1;   // clamp (discarded later)
        int tok = g_perm[e * NTOK + rr];
        arow[i] = reinterpret_cast<const float4*>(X + (size_t)tok * HDIM);
    }
    // B-load mapping: 256 float4 chunks (64 rows x 4 f4), 1 per thread
    int br = tid >> 2, bkq = tid & 3;
    const float* Bg = GW + ((size_t)e * IDIM + n0 + br) * HDIM;
    const float* Bu = UW + ((size_t)e * IDIM + n0 + br) * HDIM;

    float accG[8][4], accU[8][4];
    #pragma unroll
    for (int r = 0; r < 8; r++)
        #pragma unroll
        for (int j = 0; j < 4; j++) { accG[r][j] = 0.f; accU[r][j] = 0.f; }

    for (int kk = 0; kk < HDIM; kk += BK) {
        #pragma unroll
        for (int i = 0; i < 2; i++) {
            int c = tid + i * 256;
            int r = c >> 2;
            float4 v = arow[i][(kk >> 2) + akq[i]];
            As[akq[i] * 4 + 0][r] = v.x;
            As[akq[i] * 4 + 1][r] = v.y;
            As[akq[i] * 4 + 2][r] = v.z;
            As[akq[i] * 4 + 3][r] = v.w;
        }
        {
            float4 vg = *reinterpret_cast<const float4*>(Bg + kk + bkq * 4);
            Bgs[bkq * 4 + 0][br] = vg.x; Bgs[bkq * 4 + 1][br] = vg.y;
            Bgs[bkq * 4 + 2][br] = vg.z; Bgs[bkq * 4 + 3][br] = vg.w;
            float4 vu = *reinterpret_cast<const float4*>(Bu + kk + bkq * 4);
            Bus[bkq * 4 + 0][br] = vu.x; Bus[bkq * 4 + 1][br] = vu.y;
            Bus[bkq * 4 + 2][br] = vu.z; Bus[bkq * 4 + 3][br] = vu.w;
        }
        __syncthreads();
        #pragma unroll
        for (int k = 0; k < BK; k++) {
            float4 a0 = *reinterpret_cast<const float4*>(&As[k][ty * 8]);
            float4 a1 = *reinterpret_cast<const float4*>(&As[k][ty * 8 + 4]);
            float4 bg = *reinterpret_cast<const float4*>(&Bgs[k][tx * 4]);
            float4 bu = *reinterpret_cast<const float4*>(&Bus[k][tx * 4]);
            float a[8] = {a0.x, a0.y, a0.z, a0.w, a1.x, a1.y, a1.z, a1.w};
            float gv[4] = {bg.x, bg.y, bg.z, bg.w};
            float uv[4] = {bu.x, bu.y, bu.z, bu.w};
            #pragma unroll
            for (int r = 0; r < 8; r++) {
                #pragma unroll
                for (int j = 0; j < 4; j++) {
                    accG[r][j] = fmaf(a[r], gv[j], accG[r][j]);
                    accU[r][j] = fmaf(a[r], uv[j], accU[r][j]);
                }
            }
        }
        __syncthreads();
    }

    // epilogue: silu(g) * u
    #pragma unroll
    for (int r = 0; r < 8; r++) {
        int row = row0 + ty * 8 + r;
        if (row < M) {
            size_t gid = (size_t)(base + row);
            float4 o;
            float g0 = accG[r][0], g1 = accG[r][1], g2 = accG[r][2], g3 = accG[r][3];
            o.x = (g0 / (1.f + __expf(-g0))) * accU[r][0];
            o.y = (g1 / (1.f + __expf(-g1))) * accU[r][1];
            o.z = (g2 / (1.f + __expf(-g2))) * accU[r][2];
            o.w = (g3 / (1.f + __expf(-g3))) * accU[r][3];
            *reinterpret_cast<float4*>(&g_h[gid * IDIM + n0 + tx * 4]) = o;
        }
    }
}

// ---------------- stage 2: Y = h @ downT ----------------
// Tile: BM=128 rows, BN=128 H-cols, BK=16, 256 threads, 8x8 microtile.
#define BM2 128
#define BN2 128

__global__ __launch_bounds__(256, 2)
void gemm2_kernel(const float* __restrict__ DW) {
    int e    = blockIdx.z;
    int M    = g_count[e];
    int row0 = blockIdx.y * BM2;
    if (row0 >= M) return;
    int n0   = blockIdx.x * BN2;
    int base = g_base[e];

    __shared__ float As[BK][BM2 + 4];
    __shared__ float Bs[BK][BN2 + 4];

    int tid = threadIdx.x;
    int tx  = tid & 15;   // col group: cols n0 + tx*8 .. +7
    int ty  = tid >> 4;   // row group: rows row0 + ty*8 .. +7

    // A rows are already contiguous (compacted): g_h[base + row]
    const float4* arow[2];
    int akq[2];
    #pragma unroll
    for (int i = 0; i < 2; i++) {
        int c = tid + i * 256;
        int r = c >> 2;
        akq[i] = c & 3;
        int rr = row0 + r; if (rr > M - 1) rr = M - 1;
        arow[i] = reinterpret_cast<const float4*>(g_h + (size_t)(base + rr) * IDIM);
    }
    // B tile: 128 rows x 4 f4 = 512 chunks, 2 per thread
    const float4* brow[2];
    int bkq[2];
    #pragma unroll
    for (int i = 0; i < 2; i++) {
        int c = tid + i * 256;
        int r = c >> 2;
        bkq[i] = c & 3;
        brow[i] = reinterpret_cast<const float4*>(DW + ((size_t)e * HDIM + n0 + r) * IDIM);
    }

    float acc[8][8];
    #pragma unroll
    for (int r = 0; r < 8; r++)
        #pragma unroll
        for (int j = 0; j < 8; j++) acc[r][j] = 0.f;

    for (int kk = 0; kk < IDIM; kk += BK) {
        #pragma unroll
        for (int i = 0; i < 2; i++) {
            int c = tid + i * 256;
            int r = c >> 2;
            float4 v = arow[i][(kk >> 2) + akq[i]];
            As[akq[i] * 4 + 0][r] = v.x;
            As[akq[i] * 4 + 1][r] = v.y;
            As[akq[i] * 4 + 2][r] = v.z;
            As[akq[i] * 4 + 3][r] = v.w;
            float4 w = brow[i][(kk >> 2) + bkq[i]];
            Bs[bkq[i] * 4 + 0][r] = w.x;
            Bs[bkq[i] * 4 + 1][r] = w.y;
            Bs[bkq[i] * 4 + 2][r] = w.z;
            Bs[bkq[i] * 4 + 3][r] = w.w;
        }
        __syncthreads();
        #pragma unroll
        for (int k = 0; k < BK; k++) {
            float4 a0 = *reinterpret_cast<const float4*>(&As[k][ty * 8]);
            float4 a1 = *reinterpret_cast<const float4*>(&As[k][ty * 8 + 4]);
            float4 b0 = *reinterpret_cast<const float4*>(&Bs[k][tx * 8]);
            float4 b1 = *reinterpret_cast<const float4*>(&Bs[k][tx * 8 + 4]);
            float a[8] = {a0.x, a0.y, a0.z, a0.w, a1.x, a1.y, a1.z, a1.w};
            float b[8] = {b0.x, b0.y, b0.z, b0.w, b1.x, b1.y, b1.z, b1.w};
            #pragma unroll
            for (int r = 0; r < 8; r++)
                #pragma unroll
                for (int j = 0; j < 8; j++)
                    acc[r][j] = fmaf(a[r], b[j], acc[r][j]);
        }
        __syncthreads();
    }

    #pragma unroll
    for (int r = 0; r < 8; r++) {
        int row = row0 + ty * 8 + r;
        if (row < M) {
            size_t gid = (size_t)(base + row);
            float4 o0 = make_float4(acc[r][0], acc[r][1], acc[r][2], acc[r][3]);
            float4 o1 = make_float4(acc[r][4], acc[r][5], acc[r][6], acc[r][7]);
            *reinterpret_cast<float4*>(&g_y[gid * HDIM + n0 + tx * 8])     = o0;
            *reinterpret_cast<float4*>(&g_y[gid * HDIM + n0 + tx * 8 + 4]) = o1;
        }
    }
}

// ---------------- combine: out[n] = w0*Y[slot0] + w1*Y[slot1] ----------------
__global__ void combine_kernel(float* __restrict__ out) {
    int n = blockIdx.x;
    int c = threadIdx.x * 4;
    int e0 = g_tokexp[2 * n],     p0 = g_tokpos[2 * n];
    int e1 = g_tokexp[2 * n + 1], p1 = g_tokpos[2 * n + 1];
    float w0 = g_tokw[2 * n], w1 = g_tokw[2 * n + 1];
    size_t gid0 = (size_t)(g_base[e0] + p0);
    size_t gid1 = (size_t)(g_base[e1] + p1);
    float4 y0 = *reinterpret_cast<const float4*>(&g_y[gid0 * HDIM + c]);
    float4 y1 = *reinterpret_cast<const float4*>(&g_y[gid1 * HDIM + c]);
    float4 o;
    o.x = w0 * y0.x + w1 * y1.x;
    o.y = w0 * y0.y + w1 * y1.y;
    o.z = w0 * y0.z + w1 * y1.z;
    o.w = w0 * y0.w + w1 * y1.w;
    *reinterpret_cast<float4*>(out + (size_t)n * HDIM + c) = o;
}

// ---------------- launch ----------------
extern "C" void kernel_launch(void* const* d_in, const int* in_sizes, int n_in,
                              void* d_out, int out_size) {
    const float* X  = (const float*)d_in[0];  // hidden_states [4,4096,1024]
    const float* RW = (const float*)d_in[1];  // router_w [8,1024]
    const float* GW = (const float*)d_in[2];  // gate_w [8,2048,1024]
    const float* UW = (const float*)d_in[3];  // up_w   [8,2048,1024]
    const float* DW = (const float*)d_in[4];  // down_w [8,1024,2048]
    float* out = (float*)d_out;

    zero_counts_kernel<<<1, 32>>>();
    router_kernel<<<NTOK / 8, 256>>>(X, RW);          // 8 warps/block, 1 token/warp
    scan_base_kernel<<<1, 1>>>();
    {
        dim3 grid(IDIM / BN1, NTOK / BM1, NEXP);      // (32, 128, 8)
        gemm1_kernel<<<grid, 256>>>(X, GW, UW);
    }
    {
        dim3 grid(HDIM / BN2, NTOK / BM2, NEXP);      // (8, 128, 8)
        gemm2_kernel<<<grid, 256>>>(DW);
    }
    combine_kernel<<<NTOK, 256>>>(out);
}

// round 8
// speedup vs baseline: 2.6019x; 2.6019x over previous
#include <cuda_runtime.h>
#include <cuda_bf16.h>
#include <cstdint>
#include <math.h>

#define NTOK 16384
#define HDIM 1024
#define IDIM 2048
#define NEXP 8
#define NSLOT (2*NTOK)

// ---------------- PTX helpers (plain sm_103-safe: mma.sync + cp.async) -----
__device__ __forceinline__ uint32_t smem_u32(const void* p) {
    uint32_t a;
    asm("{ .reg .u64 t; cvta.to.shared.u64 t, %1; cvt.u32.u64 %0, t; }" : "=r"(a) : "l"(p));
    return a;
}
__device__ __forceinline__ uint32_t lds32(uint32_t a) {
    uint32_t v;
    asm volatile("ld.shared.b32 %0, [%1];" : "=r"(v) : "r"(a));
    return v;
}
#define CP16(dst, src) asm volatile("cp.async.cg.shared.global [%0], [%1], 16;" :: "r"(dst), "l"(src))
#define CP_COMMIT() asm volatile("cp.async.commit_group;" ::: "memory")
#define CP_WAIT1()  asm volatile("cp.async.wait_group 1;" ::: "memory")
#define CP_WAIT0()  asm volatile("cp.async.wait_group 0;" ::: "memory")

__device__ __forceinline__ void mma_bf16(float d[4], const uint32_t a[4], const uint32_t b[2]) {
    asm volatile("mma.sync.aligned.m16n8k16.row.col.f32.bf16.bf16.f32 "
        "{%0,%1,%2,%3}, {%4,%5,%6,%7}, {%8,%9}, {%0,%1,%2,%3};"
        : "+f"(d[0]), "+f"(d[1]), "+f"(d[2]), "+f"(d[3])
        : "r"(a[0]), "r"(a[1]), "r"(a[2]), "r"(a[3]), "r"(b[0]), "r"(b[1]));
}

// SMEM layout: 128B rows (64 bf16), 16B-chunk XOR swizzle: chunk q -> q ^ (row&7).
// kb = byte offset within the 128B row.
__device__ __forceinline__ uint32_t swoff(int row, int kb) {
    return (uint32_t)(row * 128 + ((((kb) >> 4) ^ (row & 7)) << 4) + ((kb) & 15));
}

// Fragment loads (mma.sync m16n8k16 thread mapping), conflict-free with swizzle.
__device__ __forceinline__ void ldA(uint32_t T, int m0, int kk, int lane, uint32_t a[4]) {
    int r  = m0 + (lane >> 2);
    int kb = kk * 32 + (lane & 3) * 4;
    a[0] = lds32(T + swoff(r,     kb));
    a[1] = lds32(T + swoff(r + 8, kb));
    a[2] = lds32(T + swoff(r,     kb + 16));
    a[3] = lds32(T + swoff(r + 8, kb + 16));
}
__device__ __forceinline__ void ldB(uint32_t T, int nrow0, int kk, int lane, uint32_t b[2]) {
    int r  = nrow0 + (lane >> 2);
    int kb = kk * 32 + (lane & 3) * 4;
    b[0] = lds32(T + swoff(r, kb));
    b[1] = lds32(T + swoff(r, kb + 16));
}

// ---------------- device scratch ----------------
__device__ int   g_count[NEXP];
__device__ int   g_base[NEXP + 1];
__device__ int   g_perm[NEXP * NTOK];
__device__ int   g_tokexp[NSLOT];
__device__ int   g_tokpos[NSLOT];
__device__ float g_tokw[NSLOT];
__device__ __nv_bfloat16 g_Xhi[(size_t)NTOK * HDIM],  g_Xlo[(size_t)NTOK * HDIM];
__device__ __nv_bfloat16 g_Ghi[(size_t)NEXP * IDIM * HDIM], g_Glo[(size_t)NEXP * IDIM * HDIM];
__device__ __nv_bfloat16 g_Uhi[(size_t)NEXP * IDIM * HDIM], g_Ulo[(size_t)NEXP * IDIM * HDIM];
__device__ __nv_bfloat16 g_Dhi[(size_t)NEXP * HDIM * IDIM], g_Dlo[(size_t)NEXP * HDIM * IDIM];
__device__ __nv_bfloat16 g_Hhi[(size_t)NSLOT * IDIM], g_Hlo[(size_t)NSLOT * IDIM];
__device__ float g_y[(size_t)NSLOT * HDIM];

// ---------------- small kernels ----------------
__global__ void zero_counts_kernel() { if (threadIdx.x < NEXP) g_count[threadIdx.x] = 0; }

__global__ void scan_base_kernel() {
    int b = 0; g_base[0] = 0;
    #pragma unroll
    for (int e = 0; e < NEXP; e++) { b += g_count[e]; g_base[e + 1] = b; }
}

__global__ void convert_kernel(const float* __restrict__ s,
                               __nv_bfloat16* __restrict__ hi,
                               __nv_bfloat16* __restrict__ lo, int n4) {
    int i = blockIdx.x * blockDim.x + threadIdx.x;
    if (i >= n4) return;
    float4 v = reinterpret_cast<const float4*>(s)[i];
    __nv_bfloat16 h[4], l[4];
    float f[4] = {v.x, v.y, v.z, v.w};
    #pragma unroll
    for (int j = 0; j < 4; j++) {
        h[j] = __float2bfloat16_rn(f[j]);
        l[j] = __float2bfloat16_rn(f[j] - __bfloat162float(h[j]));
    }
    reinterpret_cast<uint2*>(hi)[i] = *reinterpret_cast<uint2*>(h);
    reinterpret_cast<uint2*>(lo)[i] = *reinterpret_cast<uint2*>(l);
}

// ---------------- router ----------------
__global__ void router_kernel(const float* __restrict__ X, const float* __restrict__ RW) {
    int gwarp = (blockIdx.x * blockDim.x + threadIdx.x) >> 5;
    int lane  = threadIdx.x & 31;
    if (gwarp >= NTOK) return;
    const float4* x4 = reinterpret_cast<const float4*>(X + (size_t)gwarp * HDIM);
    float l[NEXP];
    #pragma unroll
    for (int e = 0; e < NEXP; e++) {
        const float4* w4 = reinterpret_cast<const float4*>(RW + e * HDIM);
        float s = 0.f;
        #pragma unroll
        for (int i = 0; i < 8; i++) {
            float4 a = x4[lane + 32 * i];
            float4 b = w4[lane + 32 * i];
            s += a.x * b.x + a.y * b.y + a.z * b.z + a.w * b.w;
        }
        #pragma unroll
        for (int o = 16; o > 0; o >>= 1) s += __shfl_xor_sync(0xffffffffu, s, o);
        l[e] = s;
    }
    if (lane == 0) {
        int e0 = 0; float l0 = l[0];
        #pragma unroll
        for (int e = 1; e < NEXP; e++) { if (l[e] > l0) { l0 = l[e]; e0 = e; } }
        int e1 = -1; float l1 = -1e30f;
        #pragma unroll
        for (int e = 0; e < NEXP; e++) if (e != e0 && l[e] > l1) { l1 = l[e]; e1 = e; }
        float d  = __expf(l1 - l0);
        float w0 = 1.f / (1.f + d);
        float w1 = 1.f - w0;
        int n = gwarp;
        int p0 = atomicAdd(&g_count[e0], 1);
        g_perm[e0 * NTOK + p0] = n;
        g_tokexp[2*n] = e0; g_tokpos[2*n] = p0; g_tokw[2*n] = w0;
        int p1 = atomicAdd(&g_count[e1], 1);
        g_perm[e1 * NTOK + p1] = n;
        g_tokexp[2*n+1] = e1; g_tokpos[2*n+1] = p1; g_tokw[2*n+1] = w1;
    }
}

// ---------------- stage 1: h = silu(X@gateT)*(X@upT) ----------------
// Block tile 128(M) x 64(I), BK=64. 8 warps: 4(M) x 2(N), warp tile 32x32 dual.
// SMEM/stage: Ahi,Alo 16KB each; Bgh,Bgl,Buh,Bul 8KB each = 64KB; x2 = 128KB.
#define S1_AHI 0
#define S1_ALO 16384
#define S1_BGH 32768
#define S1_BGL 40960
#define S1_BUH 49152
#define S1_BUL 57344
#define S1_STG 65536
#define SMEM1  (2 * S1_STG)

__global__ __launch_bounds__(256, 1) void gemm1_kernel() {
    int e    = blockIdx.z;
    int M    = g_count[e];
    int row0 = blockIdx.y * 128;
    if (row0 >= M) return;
    int n0   = blockIdx.x * 64;
    int base = g_base[e];

    extern __shared__ char smem[];
    uint32_t sb = smem_u32(smem);
    int tid = threadIdx.x, warp = tid >> 5, lane = tid & 31;
    int m0  = (warp >> 1) * 32;   // warp M offset in tile
    int nn0 = (warp & 1) * 32;    // warp N offset in tile

    // per-thread cp.async chunk setup
    const char* gpA[4]; uint32_t soA[4];
    #pragma unroll
    for (int i = 0; i < 4; i++) {
        int id = tid + 256 * i;         // 0..1023
        int r = id >> 3, q = id & 7;
        int ar = row0 + r; if (ar > M - 1) ar = M - 1;
        int tok = g_perm[e * NTOK + ar];
        gpA[i] = (const char*)(g_Xhi + (size_t)tok * HDIM) + q * 16;
        soA[i] = swoff(r, q * 16);
    }
    const char* gpB[2]; uint32_t soB[2];
    #pragma unroll
    for (int i = 0; i < 2; i++) {
        int id = tid + 256 * i;         // 0..511
        int r = id >> 3, q = id & 7;
        gpB[i] = (const char*)(g_Ghi + ((size_t)e * IDIM + n0 + r) * HDIM) + q * 16;
        soB[i] = swoff(r, q * 16);
    }
    const ptrdiff_t dAL = (const char*)g_Xlo - (const char*)g_Xhi;
    const ptrdiff_t dGL = (const char*)g_Glo - (const char*)g_Ghi;
    const ptrdiff_t dUH = (const char*)g_Uhi - (const char*)g_Ghi;
    const ptrdiff_t dUL = (const char*)g_Ulo - (const char*)g_Ghi;

    float accG[2][4][4], accU[2][4][4];
    #pragma unroll
    for (int a = 0; a < 2; a++)
        #pragma unroll
        for (int b = 0; b < 4; b++)
            #pragma unroll
            for (int c = 0; c < 4; c++) { accG[a][b][c] = 0.f; accU[a][b][c] = 0.f; }

    // prologue load
    {
        uint32_t B = sb;
        #pragma unroll
        for (int i = 0; i < 4; i++) {
            CP16(B + S1_AHI + soA[i], gpA[i]);
            CP16(B + S1_ALO + soA[i], gpA[i] + dAL);
        }
        #pragma unroll
        for (int i = 0; i < 2; i++) {
            CP16(B + S1_BGH + soB[i], gpB[i]);
            CP16(B + S1_BGL + soB[i], gpB[i] + dGL);
            CP16(B + S1_BUH + soB[i], gpB[i] + dUH);
            CP16(B + S1_BUL + soB[i], gpB[i] + dUL);
        }
        CP_COMMIT();
    }

    const int NC = HDIM / 64;   // 16
    for (int c = 0; c < NC; c++) {
        int s = c & 1;
        if (c + 1 < NC) {
            uint32_t B = sb + (s ^ 1) * S1_STG;
            ptrdiff_t off = (ptrdiff_t)(c + 1) * 128;
            #pragma unroll
            for (int i = 0; i < 4; i++) {
                CP16(B + S1_AHI + soA[i], gpA[i] + off);
                CP16(B + S1_ALO + soA[i], gpA[i] + dAL + off);
            }
            #pragma unroll
            for (int i = 0; i < 2; i++) {
                CP16(B + S1_BGH + soB[i], gpB[i] + off);
                CP16(B + S1_BGL + soB[i], gpB[i] + dGL + off);
                CP16(B + S1_BUH + soB[i], gpB[i] + dUH + off);
                CP16(B + S1_BUL + soB[i], gpB[i] + dUL + off);
            }
            CP_COMMIT();
            CP_WAIT1();
        } else {
            CP_WAIT0();
        }
        __syncthreads();

        uint32_t SB = sb + s * S1_STG;
        #pragma unroll
        for (int kk = 0; kk < 4; kk++) {
            uint32_t ah[2][4], al[2][4];
            ldA(SB + S1_AHI, m0,      kk, lane, ah[0]);
            ldA(SB + S1_AHI, m0 + 16, kk, lane, ah[1]);
            ldA(SB + S1_ALO, m0,      kk, lane, al[0]);
            ldA(SB + S1_ALO, m0 + 16, kk, lane, al[1]);
            #pragma unroll
            for (int nt = 0; nt < 4; nt++) {
                uint32_t bgh[2], bgl[2], buh[2], bul[2];
                int nr = nn0 + nt * 8;
                ldB(SB + S1_BGH, nr, kk, lane, bgh);
                ldB(SB + S1_BGL, nr, kk, lane, bgl);
                ldB(SB + S1_BUH, nr, kk, lane, buh);
                ldB(SB + S1_BUL, nr, kk, lane, bul);
                #pragma unroll
                for (int mt = 0; mt < 2; mt++) {
                    mma_bf16(accG[mt][nt], ah[mt], bgh);
                    mma_bf16(accG[mt][nt], ah[mt], bgl);
                    mma_bf16(accG[mt][nt], al[mt], bgh);
                    mma_bf16(accU[mt][nt], ah[mt], buh);
                    mma_bf16(accU[mt][nt], ah[mt], bul);
                    mma_bf16(accU[mt][nt], al[mt], buh);
                }
            }
        }
        __syncthreads();
    }

    // epilogue: h = silu(g) * u, write bf16 hi/lo pairs
    #pragma unroll
    for (int mt = 0; mt < 2; mt++) {
        #pragma unroll
        for (int nt = 0; nt < 4; nt++) {
            int col = n0 + nn0 + nt * 8 + (lane & 3) * 2;
            #pragma unroll
            for (int half = 0; half < 2; half++) {
                int r = row0 + m0 + mt * 16 + half * 8 + (lane >> 2);
                if (r < M) {
                    float g0 = accG[mt][nt][half * 2 + 0];
                    float g1 = accG[mt][nt][half * 2 + 1];
                    float u0 = accU[mt][nt][half * 2 + 0];
                    float u1 = accU[mt][nt][half * 2 + 1];
                    float h0 = (g0 / (1.f + __expf(-g0))) * u0;
                    float h1 = (g1 / (1.f + __expf(-g1))) * u1;
                    __nv_bfloat16 p[2], q[2];
                    p[0] = __float2bfloat16_rn(h0);
                    p[1] = __float2bfloat16_rn(h1);
                    q[0] = __float2bfloat16_rn(h0 - __bfloat162float(p[0]));
                    q[1] = __float2bfloat16_rn(h1 - __bfloat162float(p[1]));
                    size_t gid = (size_t)(base + r) * IDIM + col;
                    *reinterpret_cast<uint32_t*>(&g_Hhi[gid]) = *reinterpret_cast<uint32_t*>(p);
                    *reinterpret_cast<uint32_t*>(&g_Hlo[gid]) = *reinterpret_cast<uint32_t*>(q);
                }
            }
        }
    }
}

// ---------------- stage 2: Y = h @ downT ----------------
// Block tile 128(M) x 64(H), BK=64. Same warp layout, single accumulator.
#define S2_AHI 0
#define S2_ALO 16384
#define S2_BH  32768
#define S2_BL  40960
#define S2_STG 49152
#define SMEM2  (2 * S2_STG)

__global__ __launch_bounds__(256, 1) void gemm2_kernel() {
    int e    = blockIdx.z;
    int M    = g_count[e];
    int row0 = blockIdx.y * 128;
    if (row0 >= M) return;
    int n0   = blockIdx.x * 64;
    int base = g_base[e];

    extern __shared__ char smem[];
    uint32_t sb = smem_u32(smem);
    int tid = threadIdx.x, warp = tid >> 5, lane = tid & 31;
    int m0  = (warp >> 1) * 32;
    int nn0 = (warp & 1) * 32;

    const char* gpA[4]; uint32_t soA[4];
    #pragma unroll
    for (int i = 0; i < 4; i++) {
        int id = tid + 256 * i;
        int r = id >> 3, q = id & 7;
        int ar = row0 + r; if (ar > M - 1) ar = M - 1;
        gpA[i] = (const char*)(g_Hhi + (size_t)(base + ar) * IDIM) + q * 16;
        soA[i] = swoff(r, q * 16);
    }
    const char* gpB[2]; uint32_t soB[2];
    #pragma unroll
    for (int i = 0; i < 2; i++) {
        int id = tid + 256 * i;
        int r = id >> 3, q = id & 7;
        gpB[i] = (const char*)(g_Dhi + ((size_t)e * HDIM + n0 + r) * IDIM) + q * 16;
        soB[i] = swoff(r, q * 16);
    }
    const ptrdiff_t dAL = (const char*)g_Hlo - (const char*)g_Hhi;
    const ptrdiff_t dBL = (const char*)g_Dlo - (const char*)g_Dhi;

    float acc[2][4][4];
    #pragma unroll
    for (int a = 0; a < 2; a++)
        #pragma unroll
        for (int b = 0; b < 4; b++)
            #pragma unroll
            for (int c = 0; c < 4; c++) acc[a][b][c] = 0.f;

    {
        uint32_t B = sb;
        #pragma unroll
        for (int i = 0; i < 4; i++) {
            CP16(B + S2_AHI + soA[i], gpA[i]);
            CP16(B + S2_ALO + soA[i], gpA[i] + dAL);
        }
        #pragma unroll
        for (int i = 0; i < 2; i++) {
            CP16(B + S2_BH + soB[i], gpB[i]);
            CP16(B + S2_BL + soB[i], gpB[i] + dBL);
        }
        CP_COMMIT();
    }

    const int NC = IDIM / 64;   // 32
    for (int c = 0; c < NC; c++) {
        int s = c & 1;
        if (c + 1 < NC) {
            uint32_t B = sb + (s ^ 1) * S2_STG;
            ptrdiff_t off = (ptrdiff_t)(c + 1) * 128;
            #pragma unroll
            for (int i = 0; i < 4; i++) {
                CP16(B + S2_AHI + soA[i], gpA[i] + off);
                CP16(B + S2_ALO + soA[i], gpA[i] + dAL + off);
            }
            #pragma unroll
            for (int i = 0; i < 2; i++) {
                CP16(B + S2_BH + soB[i], gpB[i] + off);
                CP16(B + S2_BL + soB[i], gpB[i] + dBL + off);
            }
            CP_COMMIT();
            CP_WAIT1();
        } else {
            CP_WAIT0();
        }
        __syncthreads();

        uint32_t SB = sb + s * S2_STG;
        #pragma unroll
        for (int kk = 0; kk < 4; kk++) {
            uint32_t ah[2][4], al[2][4];
            ldA(SB + S2_AHI, m0,      kk, lane, ah[0]);
            ldA(SB + S2_AHI, m0 + 16, kk, lane, ah[1]);
            ldA(SB + S2_ALO, m0,      kk, lane, al[0]);
            ldA(SB + S2_ALO, m0 + 16, kk, lane, al[1]);
            #pragma unroll
            for (int nt = 0; nt < 4; nt++) {
                uint32_t bh[2], bl[2];
                int nr = nn0 + nt * 8;
                ldB(SB + S2_BH, nr, kk, lane, bh);
                ldB(SB + S2_BL, nr, kk, lane, bl);
                #pragma unroll
                for (int mt = 0; mt < 2; mt++) {
                    mma_bf16(acc[mt][nt], ah[mt], bh);
                    mma_bf16(acc[mt][nt], ah[mt], bl);
                    mma_bf16(acc[mt][nt], al[mt], bh);
                }
            }
        }
        __syncthreads();
    }

    // epilogue: fp32 y
    #pragma unroll
    for (int mt = 0; mt < 2; mt++) {
        #pragma unroll
        for (int nt = 0; nt < 4; nt++) {
            int col = n0 + nn0 + nt * 8 + (lane & 3) * 2;
            #pragma unroll
            for (int half = 0; half < 2; half++) {
                int r = row0 + m0 + mt * 16 + half * 8 + (lane >> 2);
                if (r < M) {
                    float2 o = make_float2(acc[mt][nt][half * 2 + 0], acc[mt][nt][half * 2 + 1]);
                    *reinterpret_cast<float2*>(&g_y[(size_t)(base + r) * HDIM + col]) = o;
                }
            }
        }
    }
}

// ---------------- combine ----------------
__global__ void combine_kernel(float* __restrict__ out) {
    int n = blockIdx.x;
    int c = threadIdx.x * 4;
    int e0 = g_tokexp[2*n],   p0 = g_tokpos[2*n];
    int e1 = g_tokexp[2*n+1], p1 = g_tokpos[2*n+1];
    float w0 = g_tokw[2*n], w1 = g_tokw[2*n+1];
    size_t gid0 = (size_t)(g_base[e0] + p0);
    size_t gid1 = (size_t)(g_base[e1] + p1);
    float4 y0 = *reinterpret_cast<const float4*>(&g_y[gid0 * HDIM + c]);
    float4 y1 = *reinterpret_cast<const float4*>(&g_y[gid1 * HDIM + c]);
    float4 o;
    o.x = w0 * y0.x + w1 * y1.x;
    o.y = w0 * y0.y + w1 * y1.y;
    o.z = w0 * y0.z + w1 * y1.z;
    o.w = w0 * y0.w + w1 * y1.w;
    *reinterpret_cast<float4*>(out + (size_t)n * HDIM + c) = o;
}

// ---------------- launch ----------------
extern "C" void kernel_launch(void* const* d_in, const int* in_sizes, int n_in,
                              void* d_out, int out_size) {
    const float* X  = (const float*)d_in[0];
    const float* RW = (const float*)d_in[1];
    const float* GW = (const float*)d_in[2];
    const float* UW = (const float*)d_in[3];
    const float* DW = (const float*)d_in[4];
    float* out = (float*)d_out;

    cudaFuncSetAttribute(gemm1_kernel, cudaFuncAttributeMaxDynamicSharedMemorySize, SMEM1);
    cudaFuncSetAttribute(gemm2_kernel, cudaFuncAttributeMaxDynamicSharedMemorySize, SMEM2);

    __nv_bfloat16 *xhi, *xlo, *ghi, *glo, *uhi, *ulo, *dhi, *dlo;
    cudaGetSymbolAddress((void**)&xhi, g_Xhi); cudaGetSymbolAddress((void**)&xlo, g_Xlo);
    cudaGetSymbolAddress((void**)&ghi, g_Ghi); cudaGetSymbolAddress((void**)&glo, g_Glo);
    cudaGetSymbolAddress((void**)&uhi, g_Uhi); cudaGetSymbolAddress((void**)&ulo, g_Ulo);
    cudaGetSymbolAddress((void**)&dhi, g_Dhi); cudaGetSymbolAddress((void**)&dlo, g_Dlo);

    const int nX = NTOK * HDIM / 4;
    const int nW = NEXP * IDIM * HDIM / 4;
    convert_kernel<<<(nX + 255) / 256, 256>>>(X,  xhi, xlo, nX);
    convert_kernel<<<(nW + 255) / 256, 256>>>(GW, ghi, glo, nW);
    convert_kernel<<<(nW + 255) / 256, 256>>>(UW, uhi, ulo, nW);
    convert_kernel<<<(nW + 255) / 256, 256>>>(DW, dhi, dlo, nW);

    zero_counts_kernel<<<1, 32>>>();
    router_kernel<<<NTOK / 8, 256>>>(X, RW);
    scan_base_kernel<<<1, 1>>>();

    { dim3 g(IDIM / 64, NTOK / 128, NEXP); gemm1_kernel<<<g, 256, SMEM1>>>(); }
    { dim3 g(HDIM / 64, NTOK / 128, NEXP); gemm2_kernel<<<g, 256, SMEM2>>>(); }
    combine_kernel<<<NTOK, 256>>>(out);
}

// round 9
// speedup vs baseline: 4.0030x; 1.5385x over previous
#include <cuda_runtime.h>
#include <cuda_fp16.h>
#include <cstdint>
#include <math.h>

#define NTOK 16384
#define HDIM 1024
#define IDIM 2048
#define NEXP 8
#define NSLOT (2*NTOK)

// ---------------- PTX helpers (plain sm_103-safe) ----------------
__device__ __forceinline__ uint32_t smem_u32(const void* p) {
    uint32_t a;
    asm("{ .reg .u64 t; cvta.to.shared.u64 t, %1; cvt.u32.u64 %0, t; }" : "=r"(a) : "l"(p));
    return a;
}
#define CP16(dst, src) asm volatile("cp.async.cg.shared.global [%0], [%1], 16;" :: "r"(dst), "l"(src))
#define CP_COMMIT() asm volatile("cp.async.commit_group;" ::: "memory")
#define CP_WAIT1()  asm volatile("cp.async.wait_group 1;" ::: "memory")
#define CP_WAIT0()  asm volatile("cp.async.wait_group 0;" ::: "memory")
#define LDSM4(r0, r1, r2, r3, a) \
    asm volatile("ldmatrix.sync.aligned.m8n8.x4.shared.b16 {%0,%1,%2,%3}, [%4];" \
        : "=r"(r0), "=r"(r1), "=r"(r2), "=r"(r3) : "r"(a))

__device__ __forceinline__ void mma_f16(float d[4], const uint32_t a[4], const uint32_t b[2]) {
    asm volatile("mma.sync.aligned.m16n8k16.row.col.f32.f16.f16.f32 "
        "{%0,%1,%2,%3}, {%4,%5,%6,%7}, {%8,%9}, {%0,%1,%2,%3};"
        : "+f"(d[0]), "+f"(d[1]), "+f"(d[2]), "+f"(d[3])
        : "r"(a[0]), "r"(a[1]), "r"(a[2]), "r"(a[3]), "r"(b[0]), "r"(b[1]));
}

// SMEM: 128B rows (64 fp16), 16B-chunk XOR swizzle.
__device__ __forceinline__ uint32_t swoff(int row, int kb) {
    return (uint32_t)(row * 128 + ((((kb) >> 4) ^ (row & 7)) << 4) + ((kb) & 15));
}

// ldmatrix x4 of a 16x16 fp16 tile at (row base mrow, k-byte base kb).
// Produces regs in mma m16n8k16 A order; for B, use as two n8k16 frags:
// nt_even = {r0, r2}, nt_odd = {r1, r3}.
__device__ __forceinline__ void ldm16x16(uint32_t T, int mrow, int kb, int lane, uint32_t r[4]) {
    int mat = lane >> 3, lr = lane & 7;
    uint32_t addr = T + swoff(mrow + (mat & 1) * 8 + lr, kb + (mat >> 1) * 16);
    LDSM4(r[0], r[1], r[2], r[3], addr);
}

// ---------------- device scratch ----------------
__device__ int   g_count[NEXP];
__device__ int   g_base[NEXP + 1];
__device__ int   g_perm[NEXP * NTOK];
__device__ int   g_tokexp[NSLOT];
__device__ int   g_tokpos[NSLOT];
__device__ float g_tokw[NSLOT];
__device__ __half g_Xh[(size_t)NTOK * HDIM];
__device__ __half g_Gh[(size_t)NEXP * IDIM * HDIM], g_Gl[(size_t)NEXP * IDIM * HDIM];
__device__ __half g_Uh[(size_t)NEXP * IDIM * HDIM], g_Ul[(size_t)NEXP * IDIM * HDIM];
__device__ __half g_Dh[(size_t)NEXP * HDIM * IDIM], g_Dl[(size_t)NEXP * HDIM * IDIM];
__device__ __half g_Hh[(size_t)NSLOT * IDIM];
__device__ float g_y[(size_t)NSLOT * HDIM];

// ---------------- small kernels ----------------
__global__ void zero_counts_kernel() { if (threadIdx.x < NEXP) g_count[threadIdx.x] = 0; }

__global__ void scan_base_kernel() {
    int b = 0; g_base[0] = 0;
    #pragma unroll
    for (int e = 0; e < NEXP; e++) { b += g_count[e]; g_base[e + 1] = b; }
}

// fp32 -> single fp16
__global__ void convert1_kernel(const float* __restrict__ s, __half* __restrict__ h, int n4) {
    int i = blockIdx.x * blockDim.x + threadIdx.x;
    if (i >= n4) return;
    float4 v = reinterpret_cast<const float4*>(s)[i];
    __half o[4] = {__float2half_rn(v.x), __float2half_rn(v.y),
                   __float2half_rn(v.z), __float2half_rn(v.w)};
    reinterpret_cast<uint2*>(h)[i] = *reinterpret_cast<uint2*>(o);
}

// fp32 -> fp16 hi/lo split
__global__ void convert2_kernel(const float* __restrict__ s,
                                __half* __restrict__ hi, __half* __restrict__ lo, int n4) {
    int i = blockIdx.x * blockDim.x + threadIdx.x;
    if (i >= n4) return;
    float4 v = reinterpret_cast<const float4*>(s)[i];
    float f[4] = {v.x, v.y, v.z, v.w};
    __half h[4], l[4];
    #pragma unroll
    for (int j = 0; j < 4; j++) {
        h[j] = __float2half_rn(f[j]);
        l[j] = __float2half_rn(f[j] - __half2float(h[j]));
    }
    reinterpret_cast<uint2*>(hi)[i] = *reinterpret_cast<uint2*>(h);
    reinterpret_cast<uint2*>(lo)[i] = *reinterpret_cast<uint2*>(l);
}

// ---------------- router ----------------
__global__ void router_kernel(const float* __restrict__ X, const float* __restrict__ RW) {
    int gwarp = (blockIdx.x * blockDim.x + threadIdx.x) >> 5;
    int lane  = threadIdx.x & 31;
    if (gwarp >= NTOK) return;
    const float4* x4 = reinterpret_cast<const float4*>(X + (size_t)gwarp * HDIM);
    float l[NEXP];
    #pragma unroll
    for (int e = 0; e < NEXP; e++) {
        const float4* w4 = reinterpret_cast<const float4*>(RW + e * HDIM);
        float s = 0.f;
        #pragma unroll
        for (int i = 0; i < 8; i++) {
            float4 a = x4[lane + 32 * i];
            float4 b = w4[lane + 32 * i];
            s += a.x * b.x + a.y * b.y + a.z * b.z + a.w * b.w;
        }
        #pragma unroll
        for (int o = 16; o > 0; o >>= 1) s += __shfl_xor_sync(0xffffffffu, s, o);
        l[e] = s;
    }
    if (lane == 0) {
        int e0 = 0; float l0 = l[0];
        #pragma unroll
        for (int e = 1; e < NEXP; e++) { if (l[e] > l0) { l0 = l[e]; e0 = e; } }
        int e1 = -1; float l1 = -1e30f;
        #pragma unroll
        for (int e = 0; e < NEXP; e++) if (e != e0 && l[e] > l1) { l1 = l[e]; e1 = e; }
        float d  = __expf(l1 - l0);
        float w0 = 1.f / (1.f + d);
        float w1 = 1.f - w0;
        int n = gwarp;
        int p0 = atomicAdd(&g_count[e0], 1);
        g_perm[e0 * NTOK + p0] = n;
        g_tokexp[2*n] = e0; g_tokpos[2*n] = p0; g_tokw[2*n] = w0;
        int p1 = atomicAdd(&g_count[e1], 1);
        g_perm[e1 * NTOK + p1] = n;
        g_tokexp[2*n+1] = e1; g_tokpos[2*n+1] = p1; g_tokw[2*n+1] = w1;
    }
}

// ---------------- stage 1: h = silu(X@gateT)*(X@upT) ----------------
// Block tile 128(M) x 64(I), BK=64. 8 warps 4(M)x2(N), warp tile 32x32 dual.
// Passes: a*bh + a*bl (A single fp16, B split). SMEM: A 16KB + 4x8KB B = 48KB/stage.
#define S1_A  0
#define S1_GH 16384
#define S1_GL 24576
#define S1_UH 32768
#define S1_UL 40960
#define S1_STG 49152
#define SMEM1 (2 * S1_STG)

__global__ __launch_bounds__(256, 2) void gemm1_kernel() {
    int e    = blockIdx.z;
    int M    = g_count[e];
    int row0 = blockIdx.y * 128;
    if (row0 >= M) return;
    int n0   = blockIdx.x * 64;
    int base = g_base[e];

    extern __shared__ char smem[];
    uint32_t sb = smem_u32(smem);
    int tid = threadIdx.x, warp = tid >> 5, lane = tid & 31;
    int m0  = (warp >> 1) * 32;
    int nn0 = (warp & 1) * 32;

    // cp.async setup: A 1024 chunks -> 4/thread; B 512 chunks x 4 tensors -> 2/thread each
    const char* gpA[4]; uint32_t soA[4];
    #pragma unroll
    for (int i = 0; i < 4; i++) {
        int id = tid + 256 * i;
        int r = id >> 3, q = id & 7;
        int ar = row0 + r; if (ar > M - 1) ar = M - 1;
        int tok = g_perm[e * NTOK + ar];
        gpA[i] = (const char*)(g_Xh + (size_t)tok * HDIM) + q * 16;
        soA[i] = swoff(r, q * 16);
    }
    const char* gpB[2]; uint32_t soB[2];
    #pragma unroll
    for (int i = 0; i < 2; i++) {
        int id = tid + 256 * i;
        int r = id >> 3, q = id & 7;
        gpB[i] = (const char*)(g_Gh + ((size_t)e * IDIM + n0 + r) * HDIM) + q * 16;
        soB[i] = swoff(r, q * 16);
    }
    const ptrdiff_t dGL = (const char*)g_Gl - (const char*)g_Gh;
    const ptrdiff_t dUH = (const char*)g_Uh - (const char*)g_Gh;
    const ptrdiff_t dUL = (const char*)g_Ul - (const char*)g_Gh;

    float accG[2][4][4], accU[2][4][4];
    #pragma unroll
    for (int a = 0; a < 2; a++)
        #pragma unroll
        for (int b = 0; b < 4; b++)
            #pragma unroll
            for (int c = 0; c < 4; c++) { accG[a][b][c] = 0.f; accU[a][b][c] = 0.f; }

    {
        uint32_t B = sb;
        #pragma unroll
        for (int i = 0; i < 4; i++) CP16(B + S1_A + soA[i], gpA[i]);
        #pragma unroll
        for (int i = 0; i < 2; i++) {
            CP16(B + S1_GH + soB[i], gpB[i]);
            CP16(B + S1_GL + soB[i], gpB[i] + dGL);
            CP16(B + S1_UH + soB[i], gpB[i] + dUH);
            CP16(B + S1_UL + soB[i], gpB[i] + dUL);
        }
        CP_COMMIT();
    }

    const int NC = HDIM / 64;   // 16
    for (int c = 0; c < NC; c++) {
        int s = c & 1;
        if (c + 1 < NC) {
            uint32_t B = sb + (s ^ 1) * S1_STG;
            ptrdiff_t off = (ptrdiff_t)(c + 1) * 128;
            #pragma unroll
            for (int i = 0; i < 4; i++) CP16(B + S1_A + soA[i], gpA[i] + off);
            #pragma unroll
            for (int i = 0; i < 2; i++) {
                CP16(B + S1_GH + soB[i], gpB[i] + off);
                CP16(B + S1_GL + soB[i], gpB[i] + dGL + off);
                CP16(B + S1_UH + soB[i], gpB[i] + dUH + off);
                CP16(B + S1_UL + soB[i], gpB[i] + dUL + off);
            }
            CP_COMMIT();
            CP_WAIT1();
        } else {
            CP_WAIT0();
        }
        __syncthreads();

        uint32_t SB = sb + s * S1_STG;
        #pragma unroll
        for (int kk = 0; kk < 4; kk++) {
            int kb = kk * 32;
            uint32_t a[2][4];
            ldm16x16(SB + S1_A, m0,      kb, lane, a[0]);
            ldm16x16(SB + S1_A, m0 + 16, kb, lane, a[1]);
            uint32_t gh[2][4], gl[2][4], uh[2][4], ul[2][4];
            #pragma unroll
            for (int p = 0; p < 2; p++) {
                int nr = nn0 + p * 16;
                ldm16x16(SB + S1_GH, nr, kb, lane, gh[p]);
                ldm16x16(SB + S1_GL, nr, kb, lane, gl[p]);
                ldm16x16(SB + S1_UH, nr, kb, lane, uh[p]);
                ldm16x16(SB + S1_UL, nr, kb, lane, ul[p]);
            }
            #pragma unroll
            for (int nt = 0; nt < 4; nt++) {
                int p = nt >> 1, o = nt & 1;
                uint32_t bgh[2] = {gh[p][o], gh[p][o + 2]};
                uint32_t bgl[2] = {gl[p][o], gl[p][o + 2]};
                uint32_t buh[2] = {uh[p][o], uh[p][o + 2]};
                uint32_t bul[2] = {ul[p][o], ul[p][o + 2]};
                #pragma unroll
                for (int mt = 0; mt < 2; mt++) {
                    mma_f16(accG[mt][nt], a[mt], bgh);
                    mma_f16(accG[mt][nt], a[mt], bgl);
                    mma_f16(accU[mt][nt], a[mt], buh);
                    mma_f16(accU[mt][nt], a[mt], bul);
                }
            }
        }
        __syncthreads();
    }

    // epilogue: h = silu(g) * u, write single fp16
    #pragma unroll
    for (int mt = 0; mt < 2; mt++) {
        #pragma unroll
        for (int nt = 0; nt < 4; nt++) {
            int col = n0 + nn0 + nt * 8 + (lane & 3) * 2;
            #pragma unroll
            for (int half = 0; half < 2; half++) {
                int r = row0 + m0 + mt * 16 + half * 8 + (lane >> 2);
                if (r < M) {
                    float g0 = accG[mt][nt][half * 2 + 0];
                    float g1 = accG[mt][nt][half * 2 + 1];
                    float u0 = accU[mt][nt][half * 2 + 0];
                    float u1 = accU[mt][nt][half * 2 + 1];
                    float h0 = (g0 / (1.f + __expf(-g0))) * u0;
                    float h1 = (g1 / (1.f + __expf(-g1))) * u1;
                    __half p[2] = {__float2half_rn(h0), __float2half_rn(h1)};
                    size_t gid = (size_t)(base + r) * IDIM + col;
                    *reinterpret_cast<uint32_t*>(&g_Hh[gid]) = *reinterpret_cast<uint32_t*>(p);
                }
            }
        }
    }
}

// ---------------- stage 2: Y = h @ downT ----------------
#define S2_A  0
#define S2_BH 16384
#define S2_BL 24576
#define S2_STG 32768
#define SMEM2 (2 * S2_STG)

__global__ __launch_bounds__(256, 2) void gemm2_kernel() {
    int e    = blockIdx.z;
    int M    = g_count[e];
    int row0 = blockIdx.y * 128;
    if (row0 >= M) return;
    int n0   = blockIdx.x * 64;
    int base = g_base[e];

    extern __shared__ char smem[];
    uint32_t sb = smem_u32(smem);
    int tid = threadIdx.x, warp = tid >> 5, lane = tid & 31;
    int m0  = (warp >> 1) * 32;
    int nn0 = (warp & 1) * 32;

    const char* gpA[4]; uint32_t soA[4];
    #pragma unroll
    for (int i = 0; i < 4; i++) {
        int id = tid + 256 * i;
        int r = id >> 3, q = id & 7;
        int ar = row0 + r; if (ar > M - 1) ar = M - 1;
        gpA[i] = (const char*)(g_Hh + (size_t)(base + ar) * IDIM) + q * 16;
        soA[i] = swoff(r, q * 16);
    }
    const char* gpB[2]; uint32_t soB[2];
    #pragma unroll
    for (int i = 0; i < 2; i++) {
        int id = tid + 256 * i;
        int r = id >> 3, q = id & 7;
        gpB[i] = (const char*)(g_Dh + ((size_t)e * HDIM + n0 + r) * IDIM) + q * 16;
        soB[i] = swoff(r, q * 16);
    }
    const ptrdiff_t dBL = (const char*)g_Dl - (const char*)g_Dh;

    float acc[2][4][4];
    #pragma unroll
    for (int a = 0; a < 2; a++)
        #pragma unroll
        for (int b = 0; b < 4; b++)
            #pragma unroll
            for (int c = 0; c < 4; c++) acc[a][b][c] = 0.f;

    {
        uint32_t B = sb;
        #pragma unroll
        for (int i = 0; i < 4; i++) CP16(B + S2_A + soA[i], gpA[i]);
        #pragma unroll
        for (int i = 0; i < 2; i++) {
            CP16(B + S2_BH + soB[i], gpB[i]);
            CP16(B + S2_BL + soB[i], gpB[i] + dBL);
        }
        CP_COMMIT();
    }

    const int NC = IDIM / 64;   // 32
    for (int c = 0; c < NC; c++) {
        int s = c & 1;
        if (c + 1 < NC) {
            uint32_t B = sb + (s ^ 1) * S2_STG;
            ptrdiff_t off = (ptrdiff_t)(c + 1) * 128;
            #pragma unroll
            for (int i = 0; i < 4; i++) CP16(B + S2_A + soA[i], gpA[i] + off);
            #pragma unroll
            for (int i = 0; i < 2; i++) {
                CP16(B + S2_BH + soB[i], gpB[i] + off);
                CP16(B + S2_BL + soB[i], gpB[i] + dBL + off);
            }
            CP_COMMIT();
            CP_WAIT1();
        } else {
            CP_WAIT0();
        }
        __syncthreads();

        uint32_t SB = sb + s * S2_STG;
        #pragma unroll
        for (int kk = 0; kk < 4; kk++) {
            int kb = kk * 32;
            uint32_t a[2][4];
            ldm16x16(SB + S2_A, m0,      kb, lane, a[0]);
            ldm16x16(SB + S2_A, m0 + 16, kb, lane, a[1]);
            uint32_t bh[2][4], bl[2][4];
            #pragma unroll
            for (int p = 0; p < 2; p++) {
                int nr = nn0 + p * 16;
                ldm16x16(SB + S2_BH, nr, kb, lane, bh[p]);
                ldm16x16(SB + S2_BL, nr, kb, lane, bl[p]);
            }
            #pragma unroll
            for (int nt = 0; nt < 4; nt++) {
                int p = nt >> 1, o = nt & 1;
                uint32_t vh[2] = {bh[p][o], bh[p][o + 2]};
                uint32_t vl[2] = {bl[p][o], bl[p][o + 2]};
                #pragma unroll
                for (int mt = 0; mt < 2; mt++) {
                    mma_f16(acc[mt][nt], a[mt], vh);
                    mma_f16(acc[mt][nt], a[mt], vl);
                }
            }
        }
        __syncthreads();
    }

    #pragma unroll
    for (int mt = 0; mt < 2; mt++) {
        #pragma unroll
        for (int nt = 0; nt < 4; nt++) {
            int col = n0 + nn0 + nt * 8 + (lane & 3) * 2;
            #pragma unroll
            for (int half = 0; half < 2; half++) {
                int r = row0 + m0 + mt * 16 + half * 8 + (lane >> 2);
                if (r < M) {
                    float2 o = make_float2(acc[mt][nt][half * 2 + 0], acc[mt][nt][half * 2 + 1]);
                    *reinterpret_cast<float2*>(&g_y[(size_t)(base + r) * HDIM + col]) = o;
                }
            }
        }
    }
}

// ---------------- combine ----------------
__global__ void combine_kernel(float* __restrict__ out) {
    int n = blockIdx.x;
    int c = threadIdx.x * 4;
    int e0 = g_tokexp[2*n],   p0 = g_tokpos[2*n];
    int e1 = g_tokexp[2*n+1], p1 = g_tokpos[2*n+1];
    float w0 = g_tokw[2*n], w1 = g_tokw[2*n+1];
    size_t gid0 = (size_t)(g_base[e0] + p0);
    size_t gid1 = (size_t)(g_base[e1] + p1);
    float4 y0 = *reinterpret_cast<const float4*>(&g_y[gid0 * HDIM + c]);
    float4 y1 = *reinterpret_cast<const float4*>(&g_y[gid1 * HDIM + c]);
    float4 o;
    o.x = w0 * y0.x + w1 * y1.x;
    o.y = w0 * y0.y + w1 * y1.y;
    o.z = w0 * y0.z + w1 * y1.z;
    o.w = w0 * y0.w + w1 * y1.w;
    *reinterpret_cast<float4*>(out + (size_t)n * HDIM + c) = o;
}

// ---------------- launch ----------------
extern "C" void kernel_launch(void* const* d_in, const int* in_sizes, int n_in,
                              void* d_out, int out_size) {
    const float* X  = (const float*)d_in[0];
    const float* RW = (const float*)d_in[1];
    const float* GW = (const float*)d_in[2];
    const float* UW = (const float*)d_in[3];
    const float* DW = (const float*)d_in[4];
    float* out = (float*)d_out;

    cudaFuncSetAttribute(gemm1_kernel, cudaFuncAttributeMaxDynamicSharedMemorySize, SMEM1);
    cudaFuncSetAttribute(gemm2_kernel, cudaFuncAttributeMaxDynamicSharedMemorySize, SMEM2);

    __half *xh, *gh, *gl, *uh, *ul, *dh, *dl;
    cudaGetSymbolAddress((void**)&xh, g_Xh);
    cudaGetSymbolAddress((void**)&gh, g_Gh); cudaGetSymbolAddress((void**)&gl, g_Gl);
    cudaGetSymbolAddress((void**)&uh, g_Uh); cudaGetSymbolAddress((void**)&ul, g_Ul);
    cudaGetSymbolAddress((void**)&dh, g_Dh); cudaGetSymbolAddress((void**)&dl, g_Dl);

    const int nX = NTOK * HDIM / 4;
    const int nW = NEXP * IDIM * HDIM / 4;
    convert1_kernel<<<(nX + 255) / 256, 256>>>(X,  xh, nX);
    convert2_kernel<<<(nW + 255) / 256, 256>>>(GW, gh, gl, nW);
    convert2_kernel<<<(nW + 255) / 256, 256>>>(UW, uh, ul, nW);
    convert2_kernel<<<(nW + 255) / 256, 256>>>(DW, dh, dl, nW);

    zero_counts_kernel<<<1, 32>>>();
    router_kernel<<<NTOK / 8, 256>>>(X, RW);
    scan_base_kernel<<<1, 1>>>();

    { dim3 g(IDIM / 64, NTOK / 128, NEXP); gemm1_kernel<<<g, 256, SMEM1>>>(); }
    { dim3 g(HDIM / 64, NTOK / 128, NEXP); gemm2_kernel<<<g, 256, SMEM2>>>(); }
    combine_kernel<<<NTOK, 256>>>(out);
}

// round 10
// speedup vs baseline: 5.4141x; 1.3525x over previous
#include <cuda_runtime.h>
#include <cuda_fp16.h>
#include <cstdint>
#include <math.h>

#define NTOK 16384
#define HDIM 1024
#define IDIM 2048
#define NEXP 8
#define NSLOT (2*NTOK)

// ---------------- PTX helpers (plain sm_103-safe) ----------------
__device__ __forceinline__ uint32_t smem_u32(const void* p) {
    uint32_t a;
    asm("{ .reg .u64 t; cvta.to.shared.u64 t, %1; cvt.u32.u64 %0, t; }" : "=r"(a) : "l"(p));
    return a;
}
#define CP16(dst, src) asm volatile("cp.async.cg.shared.global [%0], [%1], 16;" :: "r"(dst), "l"(src))
#define CP_COMMIT() asm volatile("cp.async.commit_group;" ::: "memory")
#define CP_WAIT1()  asm volatile("cp.async.wait_group 1;" ::: "memory")
#define CP_WAIT0()  asm volatile("cp.async.wait_group 0;" ::: "memory")
#define LDSM4(r0, r1, r2, r3, a) \
    asm volatile("ldmatrix.sync.aligned.m8n8.x4.shared.b16 {%0,%1,%2,%3}, [%4];" \
        : "=r"(r0), "=r"(r1), "=r"(r2), "=r"(r3) : "r"(a))

__device__ __forceinline__ void mma_f16(float d[4], const uint32_t a[4], const uint32_t b[2]) {
    asm volatile("mma.sync.aligned.m16n8k16.row.col.f32.f16.f16.f32 "
        "{%0,%1,%2,%3}, {%4,%5,%6,%7}, {%8,%9}, {%0,%1,%2,%3};"
        : "+f"(d[0]), "+f"(d[1]), "+f"(d[2]), "+f"(d[3])
        : "r"(a[0]), "r"(a[1]), "r"(a[2]), "r"(a[3]), "r"(b[0]), "r"(b[1]));
}

// SMEM: 128B rows (64 fp16), 16B-chunk XOR swizzle.
__device__ __forceinline__ uint32_t swoff(int row, int kb) {
    return (uint32_t)(row * 128 + ((((kb) >> 4) ^ (row & 7)) << 4) + ((kb) & 15));
}

// ldmatrix x4 of a 16x16 fp16 tile at (row base mrow, k-byte base kb).
__device__ __forceinline__ void ldm16x16(uint32_t T, int mrow, int kb, int lane, uint32_t r[4]) {
    int mat = lane >> 3, lr = lane & 7;
    uint32_t addr = T + swoff(mrow + (mat & 1) * 8 + lr, kb + (mat >> 1) * 16);
    LDSM4(r[0], r[1], r[2], r[3], addr);
}

// ---------------- device scratch ----------------
__device__ int   g_count[NEXP];
__device__ int   g_base[NEXP + 1];
__device__ int   g_perm[NEXP * NTOK];
__device__ int   g_tokexp[NSLOT];
__device__ int   g_tokpos[NSLOT];
__device__ float g_tokw[NSLOT];
__device__ __half g_Xh[(size_t)NTOK * HDIM];
__device__ __half g_Gh[(size_t)NEXP * IDIM * HDIM], g_Gl[(size_t)NEXP * IDIM * HDIM];
__device__ __half g_Uh[(size_t)NEXP * IDIM * HDIM];
__device__ __half g_Dh[(size_t)NEXP * HDIM * IDIM];
__device__ __half g_Hh[(size_t)NSLOT * IDIM];
__device__ float g_y[(size_t)NSLOT * HDIM];

// ---------------- small kernels ----------------
__global__ void zero_counts_kernel() { if (threadIdx.x < NEXP) g_count[threadIdx.x] = 0; }

__global__ void scan_base_kernel() {
    int b = 0; g_base[0] = 0;
    #pragma unroll
    for (int e = 0; e < NEXP; e++) { b += g_count[e]; g_base[e + 1] = b; }
}

// fp32 -> single fp16
__global__ void convert1_kernel(const float* __restrict__ s, __half* __restrict__ h, int n4) {
    int i = blockIdx.x * blockDim.x + threadIdx.x;
    if (i >= n4) return;
    float4 v = reinterpret_cast<const float4*>(s)[i];
    __half o[4] = {__float2half_rn(v.x), __float2half_rn(v.y),
                   __float2half_rn(v.z), __float2half_rn(v.w)};
    reinterpret_cast<uint2*>(h)[i] = *reinterpret_cast<uint2*>(o);
}

// fp32 -> fp16 hi/lo split
__global__ void convert2_kernel(const float* __restrict__ s,
                                __half* __restrict__ hi, __half* __restrict__ lo, int n4) {
    int i = blockIdx.x * blockDim.x + threadIdx.x;
    if (i >= n4) return;
    float4 v = reinterpret_cast<const float4*>(s)[i];
    float f[4] = {v.x, v.y, v.z, v.w};
    __half h[4], l[4];
    #pragma unroll
    for (int j = 0; j < 4; j++) {
        h[j] = __float2half_rn(f[j]);
        l[j] = __float2half_rn(f[j] - __half2float(h[j]));
    }
    reinterpret_cast<uint2*>(hi)[i] = *reinterpret_cast<uint2*>(h);
    reinterpret_cast<uint2*>(lo)[i] = *reinterpret_cast<uint2*>(l);
}

// ---------------- router ----------------
__global__ void router_kernel(const float* __restrict__ X, const float* __restrict__ RW) {
    int gwarp = (blockIdx.x * blockDim.x + threadIdx.x) >> 5;
    int lane  = threadIdx.x & 31;
    if (gwarp >= NTOK) return;
    const float4* x4 = reinterpret_cast<const float4*>(X + (size_t)gwarp * HDIM);
    float l[NEXP];
    #pragma unroll
    for (int e = 0; e < NEXP; e++) {
        const float4* w4 = reinterpret_cast<const float4*>(RW + e * HDIM);
        float s = 0.f;
        #pragma unroll
        for (int i = 0; i < 8; i++) {
            float4 a = x4[lane + 32 * i];
            float4 b = w4[lane + 32 * i];
            s += a.x * b.x + a.y * b.y + a.z * b.z + a.w * b.w;
        }
        #pragma unroll
        for (int o = 16; o > 0; o >>= 1) s += __shfl_xor_sync(0xffffffffu, s, o);
        l[e] = s;
    }
    if (lane == 0) {
        int e0 = 0; float l0 = l[0];
        #pragma unroll
        for (int e = 1; e < NEXP; e++) { if (l[e] > l0) { l0 = l[e]; e0 = e; } }
        int e1 = -1; float l1 = -1e30f;
        #pragma unroll
        for (int e = 0; e < NEXP; e++) if (e != e0 && l[e] > l1) { l1 = l[e]; e1 = e; }
        float d  = __expf(l1 - l0);
        float w0 = 1.f / (1.f + d);
        float w1 = 1.f - w0;
        int n = gwarp;
        int p0 = atomicAdd(&g_count[e0], 1);
        g_perm[e0 * NTOK + p0] = n;
        g_tokexp[2*n] = e0; g_tokpos[2*n] = p0; g_tokw[2*n] = w0;
        int p1 = atomicAdd(&g_count[e1], 1);
        g_perm[e1 * NTOK + p1] = n;
        g_tokexp[2*n+1] = e1; g_tokpos[2*n+1] = p1; g_tokw[2*n+1] = w1;
    }
}

// ---------------- stage 1: h = silu(X@gateT)*(X@upT) ----------------
// Block tile 128(M) x 64(I), BK=64. 8 warps 4(M)x2(N), warp tile 32x32 dual.
// Passes: gate = a*gh + a*gl (split), up = a*uh (single). 3 mma per (mt,nt).
#define S1_A  0
#define S1_GH 16384
#define S1_GL 24576
#define S1_UH 32768
#define S1_STG 40960
#define SMEM1 (2 * S1_STG)

__global__ __launch_bounds__(256, 2) void gemm1_kernel() {
    int e    = blockIdx.z;
    int M    = g_count[e];
    int row0 = blockIdx.y * 128;
    if (row0 >= M) return;
    int n0   = blockIdx.x * 64;
    int base = g_base[e];

    extern __shared__ char smem[];
    uint32_t sb = smem_u32(smem);
    int tid = threadIdx.x, warp = tid >> 5, lane = tid & 31;
    int m0  = (warp >> 1) * 32;
    int nn0 = (warp & 1) * 32;

    const char* gpA[4]; uint32_t soA[4];
    #pragma unroll
    for (int i = 0; i < 4; i++) {
        int id = tid + 256 * i;
        int r = id >> 3, q = id & 7;
        int ar = row0 + r; if (ar > M - 1) ar = M - 1;
        int tok = g_perm[e * NTOK + ar];
        gpA[i] = (const char*)(g_Xh + (size_t)tok * HDIM) + q * 16;
        soA[i] = swoff(r, q * 16);
    }
    const char* gpB[2]; uint32_t soB[2];
    #pragma unroll
    for (int i = 0; i < 2; i++) {
        int id = tid + 256 * i;
        int r = id >> 3, q = id & 7;
        gpB[i] = (const char*)(g_Gh + ((size_t)e * IDIM + n0 + r) * HDIM) + q * 16;
        soB[i] = swoff(r, q * 16);
    }
    const ptrdiff_t dGL = (const char*)g_Gl - (const char*)g_Gh;
    const ptrdiff_t dUH = (const char*)g_Uh - (const char*)g_Gh;

    float accG[2][4][4], accU[2][4][4];
    #pragma unroll
    for (int a = 0; a < 2; a++)
        #pragma unroll
        for (int b = 0; b < 4; b++)
            #pragma unroll
            for (int c = 0; c < 4; c++) { accG[a][b][c] = 0.f; accU[a][b][c] = 0.f; }

    {
        uint32_t B = sb;
        #pragma unroll
        for (int i = 0; i < 4; i++) CP16(B + S1_A + soA[i], gpA[i]);
        #pragma unroll
        for (int i = 0; i < 2; i++) {
            CP16(B + S1_GH + soB[i], gpB[i]);
            CP16(B + S1_GL + soB[i], gpB[i] + dGL);
            CP16(B + S1_UH + soB[i], gpB[i] + dUH);
        }
        CP_COMMIT();
    }

    const int NC = HDIM / 64;   // 16
    for (int c = 0; c < NC; c++) {
        int s = c & 1;
        if (c + 1 < NC) {
            uint32_t B = sb + (s ^ 1) * S1_STG;
            ptrdiff_t off = (ptrdiff_t)(c + 1) * 128;
            #pragma unroll
            for (int i = 0; i < 4; i++) CP16(B + S1_A + soA[i], gpA[i] + off);
            #pragma unroll
            for (int i = 0; i < 2; i++) {
                CP16(B + S1_GH + soB[i], gpB[i] + off);
                CP16(B + S1_GL + soB[i], gpB[i] + dGL + off);
                CP16(B + S1_UH + soB[i], gpB[i] + dUH + off);
            }
            CP_COMMIT();
            CP_WAIT1();
        } else {
            CP_WAIT0();
        }
        __syncthreads();

        uint32_t SB = sb + s * S1_STG;
        #pragma unroll
        for (int kk = 0; kk < 4; kk++) {
            int kb = kk * 32;
            uint32_t a[2][4];
            ldm16x16(SB + S1_A, m0,      kb, lane, a[0]);
            ldm16x16(SB + S1_A, m0 + 16, kb, lane, a[1]);
            uint32_t gh[2][4], gl[2][4], uh[2][4];
            #pragma unroll
            for (int p = 0; p < 2; p++) {
                int nr = nn0 + p * 16;
                ldm16x16(SB + S1_GH, nr, kb, lane, gh[p]);
                ldm16x16(SB + S1_GL, nr, kb, lane, gl[p]);
                ldm16x16(SB + S1_UH, nr, kb, lane, uh[p]);
            }
            #pragma unroll
            for (int nt = 0; nt < 4; nt++) {
                int p = nt >> 1, o = nt & 1;
                uint32_t bgh[2] = {gh[p][o], gh[p][o + 2]};
                uint32_t bgl[2] = {gl[p][o], gl[p][o + 2]};
                uint32_t buh[2] = {uh[p][o], uh[p][o + 2]};
                #pragma unroll
                for (int mt = 0; mt < 2; mt++) {
                    mma_f16(accG[mt][nt], a[mt], bgh);
                    mma_f16(accG[mt][nt], a[mt], bgl);
                    mma_f16(accU[mt][nt], a[mt], buh);
                }
            }
        }
        __syncthreads();
    }

    // epilogue: h = silu(g) * u, write single fp16
    #pragma unroll
    for (int mt = 0; mt < 2; mt++) {
        #pragma unroll
        for (int nt = 0; nt < 4; nt++) {
            int col = n0 + nn0 + nt * 8 + (lane & 3) * 2;
            #pragma unroll
            for (int half = 0; half < 2; half++) {
                int r = row0 + m0 + mt * 16 + half * 8 + (lane >> 2);
                if (r < M) {
                    float g0 = accG[mt][nt][half * 2 + 0];
                    float g1 = accG[mt][nt][half * 2 + 1];
                    float u0 = accU[mt][nt][half * 2 + 0];
                    float u1 = accU[mt][nt][half * 2 + 1];
                    float h0 = (g0 / (1.f + __expf(-g0))) * u0;
                    float h1 = (g1 / (1.f + __expf(-g1))) * u1;
                    __half p[2] = {__float2half_rn(h0), __float2half_rn(h1)};
                    size_t gid = (size_t)(base + r) * IDIM + col;
                    *reinterpret_cast<uint32_t*>(&g_Hh[gid]) = *reinterpret_cast<uint32_t*>(p);
                }
            }
        }
    }
}

// ---------------- stage 2: Y = h @ downT (single-pass fp16) ----------------
#define S2_A  0
#define S2_BH 16384
#define S2_STG 24576
#define SMEM2 (2 * S2_STG)

__global__ __launch_bounds__(256, 2) void gemm2_kernel() {
    int e    = blockIdx.z;
    int M    = g_count[e];
    int row0 = blockIdx.y * 128;
    if (row0 >= M) return;
    int n0   = blockIdx.x * 64;
    int base = g_base[e];

    extern __shared__ char smem[];
    uint32_t sb = smem_u32(smem);
    int tid = threadIdx.x, warp = tid >> 5, lane = tid & 31;
    int m0  = (warp >> 1) * 32;
    int nn0 = (warp & 1) * 32;

    const char* gpA[4]; uint32_t soA[4];
    #pragma unroll
    for (int i = 0; i < 4; i++) {
        int id = tid + 256 * i;
        int r = id >> 3, q = id & 7;
        int ar = row0 + r; if (ar > M - 1) ar = M - 1;
        gpA[i] = (const char*)(g_Hh + (size_t)(base + ar) * IDIM) + q * 16;
        soA[i] = swoff(r, q * 16);
    }
    const char* gpB[2]; uint32_t soB[2];
    #pragma unroll
    for (int i = 0; i < 2; i++) {
        int id = tid + 256 * i;
        int r = id >> 3, q = id & 7;
        gpB[i] = (const char*)(g_Dh + ((size_t)e * HDIM + n0 + r) * IDIM) + q * 16;
        soB[i] = swoff(r, q * 16);
    }

    float acc[2][4][4];
    #pragma unroll
    for (int a = 0; a < 2; a++)
        #pragma unroll
        for (int b = 0; b < 4; b++)
            #pragma unroll
            for (int c = 0; c < 4; c++) acc[a][b][c] = 0.f;

    {
        uint32_t B = sb;
        #pragma unroll
        for (int i = 0; i < 4; i++) CP16(B + S2_A + soA[i], gpA[i]);
        #pragma unroll
        for (int i = 0; i < 2; i++) CP16(B + S2_BH + soB[i], gpB[i]);
        CP_COMMIT();
    }

    const int NC = IDIM / 64;   // 32
    for (int c = 0; c < NC; c++) {
        int s = c & 1;
        if (c + 1 < NC) {
            uint32_t B = sb + (s ^ 1) * S2_STG;
            ptrdiff_t off = (ptrdiff_t)(c + 1) * 128;
            #pragma unroll
            for (int i = 0; i < 4; i++) CP16(B + S2_A + soA[i], gpA[i] + off);
            #pragma unroll
            for (int i = 0; i < 2; i++) CP16(B + S2_BH + soB[i], gpB[i] + off);
            CP_COMMIT();
            CP_WAIT1();
        } else {
            CP_WAIT0();
        }
        __syncthreads();

        uint32_t SB = sb + s * S2_STG;
        #pragma unroll
        for (int kk = 0; kk < 4; kk++) {
            int kb = kk * 32;
            uint32_t a[2][4];
            ldm16x16(SB + S2_A, m0,      kb, lane, a[0]);
            ldm16x16(SB + S2_A, m0 + 16, kb, lane, a[1]);
            uint32_t bh[2][4];
            #pragma unroll
            for (int p = 0; p < 2; p++) {
                int nr = nn0 + p * 16;
                ldm16x16(SB + S2_BH, nr, kb, lane, bh[p]);
            }
            #pragma unroll
            for (int nt = 0; nt < 4; nt++) {
                int p = nt >> 1, o = nt & 1;
                uint32_t vh[2] = {bh[p][o], bh[p][o + 2]};
                #pragma unroll
                for (int mt = 0; mt < 2; mt++) {
                    mma_f16(acc[mt][nt], a[mt], vh);
                }
            }
        }
        __syncthreads();
    }

    #pragma unroll
    for (int mt = 0; mt < 2; mt++) {
        #pragma unroll
        for (int nt = 0; nt < 4; nt++) {
            int col = n0 + nn0 + nt * 8 + (lane & 3) * 2;
            #pragma unroll
            for (int half = 0; half < 2; half++) {
                int r = row0 + m0 + mt * 16 + half * 8 + (lane >> 2);
                if (r < M) {
                    float2 o = make_float2(acc[mt][nt][half * 2 + 0], acc[mt][nt][half * 2 + 1]);
                    *reinterpret_cast<float2*>(&g_y[(size_t)(base + r) * HDIM + col]) = o;
                }
            }
        }
    }
}

// ---------------- combine ----------------
__global__ void combine_kernel(float* __restrict__ out) {
    int n = blockIdx.x;
    int c = threadIdx.x * 4;
    int e0 = g_tokexp[2*n],   p0 = g_tokpos[2*n];
    int e1 = g_tokexp[2*n+1], p1 = g_tokpos[2*n+1];
    float w0 = g_tokw[2*n], w1 = g_tokw[2*n+1];
    size_t gid0 = (size_t)(g_base[e0] + p0);
    size_t gid1 = (size_t)(g_base[e1] + p1);
    float4 y0 = *reinterpret_cast<const float4*>(&g_y[gid0 * HDIM + c]);
    float4 y1 = *reinterpret_cast<const float4*>(&g_y[gid1 * HDIM + c]);
    float4 o;
    o.x = w0 * y0.x + w1 * y1.x;
    o.y = w0 * y0.y + w1 * y1.y;
    o.z = w0 * y0.z + w1 * y1.z;
    o.w = w0 * y0.w + w1 * y1.w;
    *reinterpret_cast<float4*>(out + (size_t)n * HDIM + c) = o;
}

// ---------------- launch ----------------
extern "C" void kernel_launch(void* const* d_in, const int* in_sizes, int n_in,
                              void* d_out, int out_size) {
    const float* X  = (const float*)d_in[0];
    const float* RW = (const float*)d_in[1];
    const float* GW = (const float*)d_in[2];
    const float* UW = (const float*)d_in[3];
    const float* DW = (const float*)d_in[4];
    float* out = (float*)d_out;

    cudaFuncSetAttribute(gemm1_kernel, cudaFuncAttributeMaxDynamicSharedMemorySize, SMEM1);
    cudaFuncSetAttribute(gemm2_kernel, cudaFuncAttributeMaxDynamicSharedMemorySize, SMEM2);

    __half *xh, *gh, *gl, *uh, *dh;
    cudaGetSymbolAddress((void**)&xh, g_Xh);
    cudaGetSymbolAddress((void**)&gh, g_Gh); cudaGetSymbolAddress((void**)&gl, g_Gl);
    cudaGetSymbolAddress((void**)&uh, g_Uh);
    cudaGetSymbolAddress((void**)&dh, g_Dh);

    const int nX = NTOK * HDIM / 4;
    const int nW = NEXP * IDIM * HDIM / 4;
    convert1_kernel<<<(nX + 255) / 256, 256>>>(X,  xh, nX);
    convert2_kernel<<<(nW + 255) / 256, 256>>>(GW, gh, gl, nW);
    convert1_kernel<<<(nW + 255) / 256, 256>>>(UW, uh, nW);
    convert1_kernel<<<(nW + 255) / 256, 256>>>(DW, dh, nW);

    zero_counts_kernel<<<1, 32>>>();
    router_kernel<<<NTOK / 8, 256>>>(X, RW);
    scan_base_kernel<<<1, 1>>>();

    { dim3 g(IDIM / 64, NTOK / 128, NEXP); gemm1_kernel<<<g, 256, SMEM1>>>(); }
    { dim3 g(HDIM / 64, NTOK / 128, NEXP); gemm2_kernel<<<g, 256, SMEM2>>>(); }
    combine_kernel<<<NTOK, 256>>>(out);
}

// round 11
// speedup vs baseline: 6.6622x; 1.2305x over previous
#include <cuda_runtime.h>
#include <cuda_fp16.h>
#include <cstdint>
#include <math.h>

#define NTOK 16384
#define HDIM 1024
#define IDIM 2048
#define NEXP 8
#define NSLOT (2*NTOK)

// ---------------- PTX helpers (plain sm_103-safe) ----------------
__device__ __forceinline__ uint32_t smem_u32(const void* p) {
    uint32_t a;
    asm("{ .reg .u64 t; cvta.to.shared.u64 t, %1; cvt.u32.u64 %0, t; }" : "=r"(a) : "l"(p));
    return a;
}
#define CP16(dst, src) asm volatile("cp.async.cg.shared.global [%0], [%1], 16;" :: "r"(dst), "l"(src))
#define CP_COMMIT() asm volatile("cp.async.commit_group;" ::: "memory")
#define CP_WAIT1()  asm volatile("cp.async.wait_group 1;" ::: "memory")
#define CP_WAIT0()  asm volatile("cp.async.wait_group 0;" ::: "memory")
#define LDSM4(r0, r1, r2, r3, a) \
    asm volatile("ldmatrix.sync.aligned.m8n8.x4.shared.b16 {%0,%1,%2,%3}, [%4];" \
        : "=r"(r0), "=r"(r1), "=r"(r2), "=r"(r3) : "r"(a))

__device__ __forceinline__ void mma_f16(float d[4], const uint32_t a[4], const uint32_t b[2]) {
    asm volatile("mma.sync.aligned.m16n8k16.row.col.f32.f16.f16.f32 "
        "{%0,%1,%2,%3}, {%4,%5,%6,%7}, {%8,%9}, {%0,%1,%2,%3};"
        : "+f"(d[0]), "+f"(d[1]), "+f"(d[2]), "+f"(d[3])
        : "r"(a[0]), "r"(a[1]), "r"(a[2]), "r"(a[3]), "r"(b[0]), "r"(b[1]));
}

// SMEM: 128B rows (64 fp16), 16B-chunk XOR swizzle.
__device__ __forceinline__ uint32_t swoff(int row, int kb) {
    return (uint32_t)(row * 128 + ((((kb) >> 4) ^ (row & 7)) << 4) + ((kb) & 15));
}

// ldmatrix x4 of a 16x16 fp16 tile at (row base mrow, k-byte base kb).
__device__ __forceinline__ void ldm16x16(uint32_t T, int mrow, int kb, int lane, uint32_t r[4]) {
    int mat = lane >> 3, lr = lane & 7;
    uint32_t addr = T + swoff(mrow + (mat & 1) * 8 + lr, kb + (mat >> 1) * 16);
    LDSM4(r[0], r[1], r[2], r[3], addr);
}

// ---------------- device scratch ----------------
__device__ int   g_count[NEXP];
__device__ int   g_base[NEXP + 1];
__device__ int   g_perm[NEXP * NTOK];
__device__ int   g_tokexp[NSLOT];
__device__ int   g_tokpos[NSLOT];
__device__ float g_tokw[NSLOT];
__device__ __half g_Xh[(size_t)NTOK * HDIM];
__device__ __half g_Gh[(size_t)NEXP * IDIM * HDIM];
__device__ __half g_Uh[(size_t)NEXP * IDIM * HDIM];
__device__ __half g_Dh[(size_t)NEXP * HDIM * IDIM];
__device__ __half g_Hh[(size_t)NSLOT * IDIM];
__device__ float g_y[(size_t)NSLOT * HDIM];

// ---------------- small kernels ----------------
__global__ void zero_counts_kernel() { if (threadIdx.x < NEXP) g_count[threadIdx.x] = 0; }

__global__ void scan_base_kernel() {
    int b = 0; g_base[0] = 0;
    #pragma unroll
    for (int e = 0; e < NEXP; e++) { b += g_count[e]; g_base[e + 1] = b; }
}

// fp32 -> single fp16
__global__ void convert1_kernel(const float* __restrict__ s, __half* __restrict__ h, int n4) {
    int i = blockIdx.x * blockDim.x + threadIdx.x;
    if (i >= n4) return;
    float4 v = reinterpret_cast<const float4*>(s)[i];
    __half o[4] = {__float2half_rn(v.x), __float2half_rn(v.y),
                   __float2half_rn(v.z), __float2half_rn(v.w)};
    reinterpret_cast<uint2*>(h)[i] = *reinterpret_cast<uint2*>(o);
}

// ---------------- router ----------------
__global__ void router_kernel(const float* __restrict__ X, const float* __restrict__ RW) {
    int gwarp = (blockIdx.x * blockDim.x + threadIdx.x) >> 5;
    int lane  = threadIdx.x & 31;
    if (gwarp >= NTOK) return;
    const float4* x4 = reinterpret_cast<const float4*>(X + (size_t)gwarp * HDIM);
    float l[NEXP];
    #pragma unroll
    for (int e = 0; e < NEXP; e++) {
        const float4* w4 = reinterpret_cast<const float4*>(RW + e * HDIM);
        float s = 0.f;
        #pragma unroll
        for (int i = 0; i < 8; i++) {
            float4 a = x4[lane + 32 * i];
            float4 b = w4[lane + 32 * i];
            s += a.x * b.x + a.y * b.y + a.z * b.z + a.w * b.w;
        }
        #pragma unroll
        for (int o = 16; o > 0; o >>= 1) s += __shfl_xor_sync(0xffffffffu, s, o);
        l[e] = s;
    }
    if (lane == 0) {
        int e0 = 0; float l0 = l[0];
        #pragma unroll
        for (int e = 1; e < NEXP; e++) { if (l[e] > l0) { l0 = l[e]; e0 = e; } }
        int e1 = -1; float l1 = -1e30f;
        #pragma unroll
        for (int e = 0; e < NEXP; e++) if (e != e0 && l[e] > l1) { l1 = l[e]; e1 = e; }
        float d  = __expf(l1 - l0);
        float w0 = 1.f / (1.f + d);
        float w1 = 1.f - w0;
        int n = gwarp;
        int p0 = atomicAdd(&g_count[e0], 1);
        g_perm[e0 * NTOK + p0] = n;
        g_tokexp[2*n] = e0; g_tokpos[2*n] = p0; g_tokw[2*n] = w0;
        int p1 = atomicAdd(&g_count[e1], 1);
        g_perm[e1 * NTOK + p1] = n;
        g_tokexp[2*n+1] = e1; g_tokpos[2*n+1] = p1; g_tokw[2*n+1] = w1;
    }
}

// ---------------- stage 1: h = silu(X@gateT)*(X@upT), all-fp16 single-pass --
// Block tile 128(M) x 64(I), BK=64. 8 warps 4(M)x2(N), warp tile 32x32 dual.
#define S1_A  0
#define S1_GH 16384
#define S1_UH 24576
#define S1_STG 32768
#define SMEM1 (2 * S1_STG)

__global__ __launch_bounds__(256, 2) void gemm1_kernel() {
    int e    = blockIdx.z;
    int M    = g_count[e];
    int row0 = blockIdx.y * 128;
    if (row0 >= M) return;
    int n0   = blockIdx.x * 64;
    int base = g_base[e];

    extern __shared__ char smem[];
    uint32_t sb = smem_u32(smem);
    int tid = threadIdx.x, warp = tid >> 5, lane = tid & 31;
    int m0  = (warp >> 1) * 32;
    int nn0 = (warp & 1) * 32;

    const char* gpA[4]; uint32_t soA[4];
    #pragma unroll
    for (int i = 0; i < 4; i++) {
        int id = tid + 256 * i;
        int r = id >> 3, q = id & 7;
        int ar = row0 + r; if (ar > M - 1) ar = M - 1;
        int tok = g_perm[e * NTOK + ar];
        gpA[i] = (const char*)(g_Xh + (size_t)tok * HDIM) + q * 16;
        soA[i] = swoff(r, q * 16);
    }
    const char* gpB[2]; uint32_t soB[2];
    #pragma unroll
    for (int i = 0; i < 2; i++) {
        int id = tid + 256 * i;
        int r = id >> 3, q = id & 7;
        gpB[i] = (const char*)(g_Gh + ((size_t)e * IDIM + n0 + r) * HDIM) + q * 16;
        soB[i] = swoff(r, q * 16);
    }
    const ptrdiff_t dUH = (const char*)g_Uh - (const char*)g_Gh;

    float accG[2][4][4], accU[2][4][4];
    #pragma unroll
    for (int a = 0; a < 2; a++)
        #pragma unroll
        for (int b = 0; b < 4; b++)
            #pragma unroll
            for (int c = 0; c < 4; c++) { accG[a][b][c] = 0.f; accU[a][b][c] = 0.f; }

    {
        uint32_t B = sb;
        #pragma unroll
        for (int i = 0; i < 4; i++) CP16(B + S1_A + soA[i], gpA[i]);
        #pragma unroll
        for (int i = 0; i < 2; i++) {
            CP16(B + S1_GH + soB[i], gpB[i]);
            CP16(B + S1_UH + soB[i], gpB[i] + dUH);
        }
        CP_COMMIT();
    }

    const int NC = HDIM / 64;   // 16
    for (int c = 0; c < NC; c++) {
        int s = c & 1;
        if (c + 1 < NC) {
            uint32_t B = sb + (s ^ 1) * S1_STG;
            ptrdiff_t off = (ptrdiff_t)(c + 1) * 128;
            #pragma unroll
            for (int i = 0; i < 4; i++) CP16(B + S1_A + soA[i], gpA[i] + off);
            #pragma unroll
            for (int i = 0; i < 2; i++) {
                CP16(B + S1_GH + soB[i], gpB[i] + off);
                CP16(B + S1_UH + soB[i], gpB[i] + dUH + off);
            }
            CP_COMMIT();
            CP_WAIT1();
        } else {
            CP_WAIT0();
        }
        __syncthreads();

        uint32_t SB = sb + s * S1_STG;
        #pragma unroll
        for (int kk = 0; kk < 4; kk++) {
            int kb = kk * 32;
            uint32_t a[2][4];
            ldm16x16(SB + S1_A, m0,      kb, lane, a[0]);
            ldm16x16(SB + S1_A, m0 + 16, kb, lane, a[1]);
            uint32_t gh[2][4], uh[2][4];
            #pragma unroll
            for (int p = 0; p < 2; p++) {
                int nr = nn0 + p * 16;
                ldm16x16(SB + S1_GH, nr, kb, lane, gh[p]);
                ldm16x16(SB + S1_UH, nr, kb, lane, uh[p]);
            }
            #pragma unroll
            for (int nt = 0; nt < 4; nt++) {
                int p = nt >> 1, o = nt & 1;
                uint32_t bgh[2] = {gh[p][o], gh[p][o + 2]};
                uint32_t buh[2] = {uh[p][o], uh[p][o + 2]};
                #pragma unroll
                for (int mt = 0; mt < 2; mt++) {
                    mma_f16(accG[mt][nt], a[mt], bgh);
                    mma_f16(accU[mt][nt], a[mt], buh);
                }
            }
        }
        __syncthreads();
    }

    // epilogue: h = silu(g) * u, write single fp16
    #pragma unroll
    for (int mt = 0; mt < 2; mt++) {
        #pragma unroll
        for (int nt = 0; nt < 4; nt++) {
            int col = n0 + nn0 + nt * 8 + (lane & 3) * 2;
            #pragma unroll
            for (int half = 0; half < 2; half++) {
                int r = row0 + m0 + mt * 16 + half * 8 + (lane >> 2);
                if (r < M) {
                    float g0 = accG[mt][nt][half * 2 + 0];
                    float g1 = accG[mt][nt][half * 2 + 1];
                    float u0 = accU[mt][nt][half * 2 + 0];
                    float u1 = accU[mt][nt][half * 2 + 1];
                    float h0 = (g0 / (1.f + __expf(-g0))) * u0;
                    float h1 = (g1 / (1.f + __expf(-g1))) * u1;
                    __half p[2] = {__float2half_rn(h0), __float2half_rn(h1)};
                    size_t gid = (size_t)(base + r) * IDIM + col;
                    *reinterpret_cast<uint32_t*>(&g_Hh[gid]) = *reinterpret_cast<uint32_t*>(p);
                }
            }
        }
    }
}

// ---------------- stage 2: Y = h @ downT (single-pass fp16) ----------------
#define S2_A  0
#define S2_BH 16384
#define S2_STG 24576
#define SMEM2 (2 * S2_STG)

__global__ __launch_bounds__(256, 2) void gemm2_kernel() {
    int e    = blockIdx.z;
    int M    = g_count[e];
    int row0 = blockIdx.y * 128;
    if (row0 >= M) return;
    int n0   = blockIdx.x * 64;
    int base = g_base[e];

    extern __shared__ char smem[];
    uint32_t sb = smem_u32(smem);
    int tid = threadIdx.x, warp = tid >> 5, lane = tid & 31;
    int m0  = (warp >> 1) * 32;
    int nn0 = (warp & 1) * 32;

    const char* gpA[4]; uint32_t soA[4];
    #pragma unroll
    for (int i = 0; i < 4; i++) {
        int id = tid + 256 * i;
        int r = id >> 3, q = id & 7;
        int ar = row0 + r; if (ar > M - 1) ar = M - 1;
        gpA[i] = (const char*)(g_Hh + (size_t)(base + ar) * IDIM) + q * 16;
        soA[i] = swoff(r, q * 16);
    }
    const char* gpB[2]; uint32_t soB[2];
    #pragma unroll
    for (int i = 0; i < 2; i++) {
        int id = tid + 256 * i;
        int r = id >> 3, q = id & 7;
        gpB[i] = (const char*)(g_Dh + ((size_t)e * HDIM + n0 + r) * IDIM) + q * 16;
        soB[i] = swoff(r, q * 16);
    }

    float acc[2][4][4];
    #pragma unroll
    for (int a = 0; a < 2; a++)
        #pragma unroll
        for (int b = 0; b < 4; b++)
            #pragma unroll
            for (int c = 0; c < 4; c++) acc[a][b][c] = 0.f;

    {
        uint32_t B = sb;
        #pragma unroll
        for (int i = 0; i < 4; i++) CP16(B + S2_A + soA[i], gpA[i]);
        #pragma unroll
        for (int i = 0; i < 2; i++) CP16(B + S2_BH + soB[i], gpB[i]);
        CP_COMMIT();
    }

    const int NC = IDIM / 64;   // 32
    for (int c = 0; c < NC; c++) {
        int s = c & 1;
        if (c + 1 < NC) {
            uint32_t B = sb + (s ^ 1) * S2_STG;
            ptrdiff_t off = (ptrdiff_t)(c + 1) * 128;
            #pragma unroll
            for (int i = 0; i < 4; i++) CP16(B + S2_A + soA[i], gpA[i] + off);
            #pragma unroll
            for (int i = 0; i < 2; i++) CP16(B + S2_BH + soB[i], gpB[i] + off);
            CP_COMMIT();
            CP_WAIT1();
        } else {
            CP_WAIT0();
        }
        __syncthreads();

        uint32_t SB = sb + s * S2_STG;
        #pragma unroll
        for (int kk = 0; kk < 4; kk++) {
            int kb = kk * 32;
            uint32_t a[2][4];
            ldm16x16(SB + S2_A, m0,      kb, lane, a[0]);
            ldm16x16(SB + S2_A, m0 + 16, kb, lane, a[1]);
            uint32_t bh[2][4];
            #pragma unroll
            for (int p = 0; p < 2; p++) {
                int nr = nn0 + p * 16;
                ldm16x16(SB + S2_BH, nr, kb, lane, bh[p]);
            }
            #pragma unroll
            for (int nt = 0; nt < 4; nt++) {
                int p = nt >> 1, o = nt & 1;
                uint32_t vh[2] = {bh[p][o], bh[p][o + 2]};
                #pragma unroll
                for (int mt = 0; mt < 2; mt++) {
                    mma_f16(acc[mt][nt], a[mt], vh);
                }
            }
        }
        __syncthreads();
    }

    #pragma unroll
    for (int mt = 0; mt < 2; mt++) {
        #pragma unroll
        for (int nt = 0; nt < 4; nt++) {
            int col = n0 + nn0 + nt * 8 + (lane & 3) * 2;
            #pragma unroll
            for (int half = 0; half < 2; half++) {
                int r = row0 + m0 + mt * 16 + half * 8 + (lane >> 2);
                if (r < M) {
                    float2 o = make_float2(acc[mt][nt][half * 2 + 0], acc[mt][nt][half * 2 + 1]);
                    *reinterpret_cast<float2*>(&g_y[(size_t)(base + r) * HDIM + col]) = o;
                }
            }
        }
    }
}

// ---------------- combine ----------------
__global__ void combine_kernel(float* __restrict__ out) {
    int n = blockIdx.x;
    int c = threadIdx.x * 4;
    int e0 = g_tokexp[2*n],   p0 = g_tokpos[2*n];
    int e1 = g_tokexp[2*n+1], p1 = g_tokpos[2*n+1];
    float w0 = g_tokw[2*n], w1 = g_tokw[2*n+1];
    size_t gid0 = (size_t)(g_base[e0] + p0);
    size_t gid1 = (size_t)(g_base[e1] + p1);
    float4 y0 = *reinterpret_cast<const float4*>(&g_y[gid0 * HDIM + c]);
    float4 y1 = *reinterpret_cast<const float4*>(&g_y[gid1 * HDIM + c]);
    float4 o;
    o.x = w0 * y0.x + w1 * y1.x;
    o.y = w0 * y0.y + w1 * y1.y;
    o.z = w0 * y0.z + w1 * y1.z;
    o.w = w0 * y0.w + w1 * y1.w;
    *reinterpret_cast<float4*>(out + (size_t)n * HDIM + c) = o;
}

// ---------------- launch ----------------
extern "C" void kernel_launch(void* const* d_in, const int* in_sizes, int n_in,
                              void* d_out, int out_size) {
    const float* X  = (const float*)d_in[0];
    const float* RW = (const float*)d_in[1];
    const float* GW = (const float*)d_in[2];
    const float* UW = (const float*)d_in[3];
    const float* DW = (const float*)d_in[4];
    float* out = (float*)d_out;

    cudaFuncSetAttribute(gemm1_kernel, cudaFuncAttributeMaxDynamicSharedMemorySize, SMEM1);
    cudaFuncSetAttribute(gemm2_kernel, cudaFuncAttributeMaxDynamicSharedMemorySize, SMEM2);

    __half *xh, *gh, *uh, *dh;
    cudaGetSymbolAddress((void**)&xh, g_Xh);
    cudaGetSymbolAddress((void**)&gh, g_Gh);
    cudaGetSymbolAddress((void**)&uh, g_Uh);
    cudaGetSymbolAddress((void**)&dh, g_Dh);

    const int nX = NTOK * HDIM / 4;
    const int nW = NEXP * IDIM * HDIM / 4;
    convert1_kernel<<<(nX + 255) / 256, 256>>>(X,  xh, nX);
    convert1_kernel<<<(nW + 255) / 256, 256>>>(GW, gh, nW);
    convert1_kernel<<<(nW + 255) / 256, 256>>>(UW, uh, nW);
    convert1_kernel<<<(nW + 255) / 256, 256>>>(DW, dh, nW);

    zero_counts_kernel<<<1, 32>>>();
    router_kernel<<<NTOK / 8, 256>>>(X, RW);
    scan_base_kernel<<<1, 1>>>();

    { dim3 g(IDIM / 64, NTOK / 128, NEXP); gemm1_kernel<<<g, 256, SMEM1>>>(); }
    { dim3 g(HDIM / 64, NTOK / 128, NEXP); gemm2_kernel<<<g, 256, SMEM2>>>(); }
    combine_kernel<<<NTOK, 256>>>(out);
}

// round 13
// speedup vs baseline: 6.6926x; 1.0046x over previous
#include <cuda_runtime.h>
#include <cuda_fp16.h>
#include <cstdint>
#include <math.h>

#define NTOK 16384
#define HDIM 1024
#define IDIM 2048
#define NEXP 8
#define NSLOT (2*NTOK)

// ---------------- PTX helpers (plain sm_103-safe) ----------------
__device__ __forceinline__ uint32_t smem_u32(const void* p) {
    uint32_t a;
    asm("{ .reg .u64 t; cvta.to.shared.u64 t, %1; cvt.u32.u64 %0, t; }" : "=r"(a) : "l"(p));
    return a;
}
#define CP16(dst, src) asm volatile("cp.async.cg.shared.global [%0], [%1], 16;" :: "r"(dst), "l"(src))
#define CP_COMMIT() asm volatile("cp.async.commit_group;" ::: "memory")
#define CP_WAIT1()  asm volatile("cp.async.wait_group 1;" ::: "memory")
#define CP_WAIT0()  asm volatile("cp.async.wait_group 0;" ::: "memory")
#define LDSM4(r0, r1, r2, r3, a) \
    asm volatile("ldmatrix.sync.aligned.m8n8.x4.shared.b16 {%0,%1,%2,%3}, [%4];" \
        : "=r"(r0), "=r"(r1), "=r"(r2), "=r"(r3) : "r"(a))

__device__ __forceinline__ void mma_f16(float d[4], const uint32_t a[4], const uint32_t b[2]) {
    asm volatile("mma.sync.aligned.m16n8k16.row.col.f32.f16.f16.f32 "
        "{%0,%1,%2,%3}, {%4,%5,%6,%7}, {%8,%9}, {%0,%1,%2,%3};"
        : "+f"(d[0]), "+f"(d[1]), "+f"(d[2]), "+f"(d[3])
        : "r"(a[0]), "r"(a[1]), "r"(a[2]), "r"(a[3]), "r"(b[0]), "r"(b[1]));
}

// SMEM: 128B rows (64 fp16), 16B-chunk XOR swizzle.
__device__ __forceinline__ uint32_t swoff(int row, int kb) {
    return (uint32_t)(row * 128 + ((((kb) >> 4) ^ (row & 7)) << 4) + ((kb) & 15));
}

// ldmatrix x4 of a 16x16 fp16 tile at (row base mrow, k-byte base kb).
__device__ __forceinline__ void ldm16x16(uint32_t T, int mrow, int kb, int lane, uint32_t r[4]) {
    int mat = lane >> 3, lr = lane & 7;
    uint32_t addr = T + swoff(mrow + (mat & 1) * 8 + lr, kb + (mat >> 1) * 16);
    LDSM4(r[0], r[1], r[2], r[3], addr);
}

// ---------------- device scratch ----------------
__device__ int   g_count[NEXP];
__device__ int   g_base[NEXP + 1];
__device__ int   g_perm[NEXP * NTOK];
__device__ int   g_tokexp[NSLOT];
__device__ int   g_tokpos[NSLOT];
__device__ float g_tokw[NSLOT];
__device__ __half g_Xh[(size_t)NTOK * HDIM];
__device__ __half g_Gh[(size_t)NEXP * IDIM * HDIM];
__device__ __half g_Uh[(size_t)NEXP * IDIM * HDIM];
__device__ __half g_Dh[(size_t)NEXP * HDIM * IDIM];
__device__ __half g_Hh[(size_t)NSLOT * IDIM];
__device__ float g_y[(size_t)NSLOT * HDIM];

// ---------------- small kernels ----------------
__global__ void zero_counts_kernel() { if (threadIdx.x < NEXP) g_count[threadIdx.x] = 0; }

__global__ void scan_base_kernel() {
    int b = 0; g_base[0] = 0;
    #pragma unroll
    for (int e = 0; e < NEXP; e++) { b += g_count[e]; g_base[e + 1] = b; }
}

// fp32 -> single fp16
__global__ void convert1_kernel(const float* __restrict__ s, __half* __restrict__ h, int n4) {
    int i = blockIdx.x * blockDim.x + threadIdx.x;
    if (i >= n4) return;
    float4 v = reinterpret_cast<const float4*>(s)[i];
    __half o[4] = {__float2half_rn(v.x), __float2half_rn(v.y),
                   __float2half_rn(v.z), __float2half_rn(v.w)};
    reinterpret_cast<uint2*>(h)[i] = *reinterpret_cast<uint2*>(o);
}

// ---------------- router ----------------
__global__ void router_kernel(const float* __restrict__ X, const float* __restrict__ RW) {
    int gwarp = (blockIdx.x * blockDim.x + threadIdx.x) >> 5;
    int lane  = threadIdx.x & 31;
    if (gwarp >= NTOK) return;
    const float4* x4 = reinterpret_cast<const float4*>(X + (size_t)gwarp * HDIM);
    float l[NEXP];
    #pragma unroll
    for (int e = 0; e < NEXP; e++) {
        const float4* w4 = reinterpret_cast<const float4*>(RW + e * HDIM);
        float s = 0.f;
        #pragma unroll
        for (int i = 0; i < 8; i++) {
            float4 a = x4[lane + 32 * i];
            float4 b = w4[lane + 32 * i];
            s += a.x * b.x + a.y * b.y + a.z * b.z + a.w * b.w;
        }
        #pragma unroll
        for (int o = 16; o > 0; o >>= 1) s += __shfl_xor_sync(0xffffffffu, s, o);
        l[e] = s;
    }
    if (lane == 0) {
        int e0 = 0; float l0 = l[0];
        #pragma unroll
        for (int e = 1; e < NEXP; e++) { if (l[e] > l0) { l0 = l[e]; e0 = e; } }
        int e1 = -1; float l1 = -1e30f;
        #pragma unroll
        for (int e = 0; e < NEXP; e++) if (e != e0 && l[e] > l1) { l1 = l[e]; e1 = e; }
        float d  = __expf(l1 - l0);
        float w0 = 1.f / (1.f + d);
        float w1 = 1.f - w0;
        int n = gwarp;
        int p0 = atomicAdd(&g_count[e0], 1);
        g_perm[e0 * NTOK + p0] = n;
        g_tokexp[2*n] = e0; g_tokpos[2*n] = p0; g_tokw[2*n] = w0;
        int p1 = atomicAdd(&g_count[e1], 1);
        g_perm[e1 * NTOK + p1] = n;
        g_tokexp[2*n+1] = e1; g_tokpos[2*n+1] = p1; g_tokw[2*n+1] = w1;
    }
}

// ---------------- stage 1: h = silu(X@gateT)*(X@upT), fp16, 3-stage -------
// Block tile 128(M) x 64(I), BK=64. 8 warps 4(M)x2(N), warp tile 32x32 dual.
#define S1_A  0
#define S1_GH 16384
#define S1_UH 24576
#define S1_STG 32768
#define SMEM1 (3 * S1_STG)

__global__ __launch_bounds__(256, 2) void gemm1_kernel() {
    int e    = blockIdx.z;
    int M    = g_count[e];
    int row0 = blockIdx.y * 128;
    if (row0 >= M) return;
    int n0   = blockIdx.x * 64;
    int base = g_base[e];

    extern __shared__ char smem[];
    uint32_t sb = smem_u32(smem);
    int tid = threadIdx.x, warp = tid >> 5, lane = tid & 31;
    int m0  = (warp >> 1) * 32;
    int nn0 = (warp & 1) * 32;

    const char* gpA[4]; uint32_t soA[4];
    #pragma unroll
    for (int i = 0; i < 4; i++) {
        int id = tid + 256 * i;
        int r = id >> 3, q = id & 7;
        int ar = row0 + r; if (ar > M - 1) ar = M - 1;
        int tok = g_perm[e * NTOK + ar];
        gpA[i] = (const char*)(g_Xh + (size_t)tok * HDIM) + q * 16;
        soA[i] = swoff(r, q * 16);
    }
    const char* gpB[2]; uint32_t soB[2];
    #pragma unroll
    for (int i = 0; i < 2; i++) {
        int id = tid + 256 * i;
        int r = id >> 3, q = id & 7;
        gpB[i] = (const char*)(g_Gh + ((size_t)e * IDIM + n0 + r) * HDIM) + q * 16;
        soB[i] = swoff(r, q * 16);
    }
    const ptrdiff_t dUH = (const char*)g_Uh - (const char*)g_Gh;

    float accG[2][4][4], accU[2][4][4];
    #pragma unroll
    for (int a = 0; a < 2; a++)
        #pragma unroll
        for (int b = 0; b < 4; b++)
            #pragma unroll
            for (int c = 0; c < 4; c++) { accG[a][b][c] = 0.f; accU[a][b][c] = 0.f; }

    const int NC = HDIM / 64;   // 16

    // prologue: issue stages 0,1
    #pragma unroll
    for (int p = 0; p < 2; p++) {
        uint32_t B = sb + p * S1_STG;
        ptrdiff_t off = (ptrdiff_t)p * 128;
        #pragma unroll
        for (int i = 0; i < 4; i++) CP16(B + S1_A + soA[i], gpA[i] + off);
        #pragma unroll
        for (int i = 0; i < 2; i++) {
            CP16(B + S1_GH + soB[i], gpB[i] + off);
            CP16(B + S1_UH + soB[i], gpB[i] + dUH + off);
        }
        CP_COMMIT();
    }

    int sc = 0;                 // stage index of current iter (mod 3)
    for (int c = 0; c < NC; c++) {
        // Tail fix: at the final iteration the newest committed group IS this
        // stage -> must drain fully (wait_group 0), not wait_group 1.
        if (c + 1 < NC) { CP_WAIT1(); } else { CP_WAIT0(); }
        __syncthreads();        // publish stage c; license reuse of buf (c+2)%3

        if (c + 2 < NC) {
            int sn = sc + 2; if (sn >= 3) sn -= 3;
            uint32_t B = sb + sn * S1_STG;
            ptrdiff_t off = (ptrdiff_t)(c + 2) * 128;
            #pragma unroll
            for (int i = 0; i < 4; i++) CP16(B + S1_A + soA[i], gpA[i] + off);
            #pragma unroll
            for (int i = 0; i < 2; i++) {
                CP16(B + S1_GH + soB[i], gpB[i] + off);
                CP16(B + S1_UH + soB[i], gpB[i] + dUH + off);
            }
            CP_COMMIT();
        }

        uint32_t SB = sb + sc * S1_STG;
        #pragma unroll
        for (int kk = 0; kk < 4; kk++) {
            int kb = kk * 32;
            uint32_t a[2][4];
            ldm16x16(SB + S1_A, m0,      kb, lane, a[0]);
            ldm16x16(SB + S1_A, m0 + 16, kb, lane, a[1]);
            uint32_t gh[2][4], uh[2][4];
            #pragma unroll
            for (int p = 0; p < 2; p++) {
                int nr = nn0 + p * 16;
                ldm16x16(SB + S1_GH, nr, kb, lane, gh[p]);
                ldm16x16(SB + S1_UH, nr, kb, lane, uh[p]);
            }
            #pragma unroll
            for (int nt = 0; nt < 4; nt++) {
                int p = nt >> 1, o = nt & 1;
                uint32_t bgh[2] = {gh[p][o], gh[p][o + 2]};
                uint32_t buh[2] = {uh[p][o], uh[p][o + 2]};
                #pragma unroll
                for (int mt = 0; mt < 2; mt++) {
                    mma_f16(accG[mt][nt], a[mt], bgh);
                    mma_f16(accU[mt][nt], a[mt], buh);
                }
            }
        }
        if (++sc >= 3) sc = 0;
    }

    // epilogue: h = silu(g) * u, write single fp16
    #pragma unroll
    for (int mt = 0; mt < 2; mt++) {
        #pragma unroll
        for (int nt = 0; nt < 4; nt++) {
            int col = n0 + nn0 + nt * 8 + (lane & 3) * 2;
            #pragma unroll
            for (int half = 0; half < 2; half++) {
                int r = row0 + m0 + mt * 16 + half * 8 + (lane >> 2);
                if (r < M) {
                    float g0 = accG[mt][nt][half * 2 + 0];
                    float g1 = accG[mt][nt][half * 2 + 1];
                    float u0 = accU[mt][nt][half * 2 + 0];
                    float u1 = accU[mt][nt][half * 2 + 1];
                    float h0 = (g0 / (1.f + __expf(-g0))) * u0;
                    float h1 = (g1 / (1.f + __expf(-g1))) * u1;
                    __half p[2] = {__float2half_rn(h0), __float2half_rn(h1)};
                    size_t gid = (size_t)(base + r) * IDIM + col;
                    *reinterpret_cast<uint32_t*>(&g_Hh[gid]) = *reinterpret_cast<uint32_t*>(p);
                }
            }
        }
    }
}

// ---------------- stage 2: Y = h @ downT (fp16, 3-stage) ----------------
#define S2_A  0
#define S2_BH 16384
#define S2_STG 24576
#define SMEM2 (3 * S2_STG)

__global__ __launch_bounds__(256, 2) void gemm2_kernel() {
    int e    = blockIdx.z;
    int M    = g_count[e];
    int row0 = blockIdx.y * 128;
    if (row0 >= M) return;
    int n0   = blockIdx.x * 64;
    int base = g_base[e];

    extern __shared__ char smem[];
    uint32_t sb = smem_u32(smem);
    int tid = threadIdx.x, warp = tid >> 5, lane = tid & 31;
    int m0  = (warp >> 1) * 32;
    int nn0 = (warp & 1) * 32;

    const char* gpA[4]; uint32_t soA[4];
    #pragma unroll
    for (int i = 0; i < 4; i++) {
        int id = tid + 256 * i;
        int r = id >> 3, q = id & 7;
        int ar = row0 + r; if (ar > M - 1) ar = M - 1;
        gpA[i] = (const char*)(g_Hh + (size_t)(base + ar) * IDIM) + q * 16;
        soA[i] = swoff(r, q * 16);
    }
    const char* gpB[2]; uint32_t soB[2];
    #pragma unroll
    for (int i = 0; i < 2; i++) {
        int id = tid + 256 * i;
        int r = id >> 3, q = id & 7;
        gpB[i] = (const char*)(g_Dh + ((size_t)e * HDIM + n0 + r) * IDIM) + q * 16;
        soB[i] = swoff(r, q * 16);
    }

    float acc[2][4][4];
    #pragma unroll
    for (int a = 0; a < 2; a++)
        #pragma unroll
        for (int b = 0; b < 4; b++)
            #pragma unroll
            for (int c = 0; c < 4; c++) acc[a][b][c] = 0.f;

    const int NC = IDIM / 64;   // 32

    #pragma unroll
    for (int p = 0; p < 2; p++) {
        uint32_t B = sb + p * S2_STG;
        ptrdiff_t off = (ptrdiff_t)p * 128;
        #pragma unroll
        for (int i = 0; i < 4; i++) CP16(B + S2_A + soA[i], gpA[i] + off);
        #pragma unroll
        for (int i = 0; i < 2; i++) CP16(B + S2_BH + soB[i], gpB[i] + off);
        CP_COMMIT();
    }

    int sc = 0;
    for (int c = 0; c < NC; c++) {
        if (c + 1 < NC) { CP_WAIT1(); } else { CP_WAIT0(); }   // tail fix
        __syncthreads();

        if (c + 2 < NC) {
            int sn = sc + 2; if (sn >= 3) sn -= 3;
            uint32_t B = sb + sn * S2_STG;
            ptrdiff_t off = (ptrdiff_t)(c + 2) * 128;
            #pragma unroll
            for (int i = 0; i < 4; i++) CP16(B + S2_A + soA[i], gpA[i] + off);
            #pragma unroll
            for (int i = 0; i < 2; i++) CP16(B + S2_BH + soB[i], gpB[i] + off);
            CP_COMMIT();
        }

        uint32_t SB = sb + sc * S2_STG;
        #pragma unroll
        for (int kk = 0; kk < 4; kk++) {
            int kb = kk * 32;
            uint32_t a[2][4];
            ldm16x16(SB + S2_A, m0,      kb, lane, a[0]);
            ldm16x16(SB + S2_A, m0 + 16, kb, lane, a[1]);
            uint32_t bh[2][4];
            #pragma unroll
            for (int p = 0; p < 2; p++) {
                int nr = nn0 + p * 16;
                ldm16x16(SB + S2_BH, nr, kb, lane, bh[p]);
            }
            #pragma unroll
            for (int nt = 0; nt < 4; nt++) {
                int p = nt >> 1, o = nt & 1;
                uint32_t vh[2] = {bh[p][o], bh[p][o + 2]};
                #pragma unroll
                for (int mt = 0; mt < 2; mt++) {
                    mma_f16(acc[mt][nt], a[mt], vh);
                }
            }
        }
        if (++sc >= 3) sc = 0;
    }

    #pragma unroll
    for (int mt = 0; mt < 2; mt++) {
        #pragma unroll
        for (int nt = 0; nt < 4; nt++) {
            int col = n0 + nn0 + nt * 8 + (lane & 3) * 2;
            #pragma unroll
            for (int half = 0; half < 2; half++) {
                int r = row0 + m0 + mt * 16 + half * 8 + (lane >> 2);
                if (r < M) {
                    float2 o = make_float2(acc[mt][nt][half * 2 + 0], acc[mt][nt][half * 2 + 1]);
                    *reinterpret_cast<float2*>(&g_y[(size_t)(base + r) * HDIM + col]) = o;
                }
            }
        }
    }
}

// ---------------- combine ----------------
__global__ void combine_kernel(float* __restrict__ out) {
    int n = blockIdx.x;
    int c = threadIdx.x * 4;
    int e0 = g_tokexp[2*n],   p0 = g_tokpos[2*n];
    int e1 = g_tokexp[2*n+1], p1 = g_tokpos[2*n+1];
    float w0 = g_tokw[2*n], w1 = g_tokw[2*n+1];
    size_t gid0 = (size_t)(g_base[e0] + p0);
    size_t gid1 = (size_t)(g_base[e1] + p1);
    float4 y0 = *reinterpret_cast<const float4*>(&g_y[gid0 * HDIM + c]);
    float4 y1 = *reinterpret_cast<const float4*>(&g_y[gid1 * HDIM + c]);
    float4 o;
    o.x = w0 * y0.x + w1 * y1.x;
    o.y = w0 * y0.y + w1 * y1.y;
    o.z = w0 * y0.z + w1 * y1.z;
    o.w = w0 * y0.w + w1 * y1.w;
    *reinterpret_cast<float4*>(out + (size_t)n * HDIM + c) = o;
}

// ---------------- launch ----------------
extern "C" void kernel_launch(void* const* d_in, const int* in_sizes, int n_in,
                              void* d_out, int out_size) {
    const float* X  = (const float*)d_in[0];
    const float* RW = (const float*)d_in[1];
    const float* GW = (const float*)d_in[2];
    const float* UW = (const float*)d_in[3];
    const float* DW = (const float*)d_in[4];
    float* out = (float*)d_out;

    cudaFuncSetAttribute(gemm1_kernel, cudaFuncAttributeMaxDynamicSharedMemorySize, SMEM1);
    cudaFuncSetAttribute(gemm2_kernel, cudaFuncAttributeMaxDynamicSharedMemorySize, SMEM2);

    __half *xh, *gh, *uh, *dh;
    cudaGetSymbolAddress((void**)&xh, g_Xh);
    cudaGetSymbolAddress((void**)&gh, g_Gh);
    cudaGetSymbolAddress((void**)&uh, g_Uh);
    cudaGetSymbolAddress((void**)&dh, g_Dh);

    const int nX = NTOK * HDIM / 4;
    const int nW = NEXP * IDIM * HDIM / 4;
    convert1_kernel<<<(nX + 255) / 256, 256>>>(X,  xh, nX);
    convert1_kernel<<<(nW + 255) / 256, 256>>>(GW, gh, nW);
    convert1_kernel<<<(nW + 255) / 256, 256>>>(UW, uh, nW);
    convert1_kernel<<<(nW + 255) / 256, 256>>>(DW, dh, nW);

    zero_counts_kernel<<<1, 32>>>();
    router_kernel<<<NTOK / 8, 256>>>(X, RW);
    scan_base_kernel<<<1, 1>>>();

    { dim3 g(IDIM / 64, NTOK / 128, NEXP); gemm1_kernel<<<g, 256, SMEM1>>>(); }
    { dim3 g(HDIM / 64, NTOK / 128, NEXP); gemm2_kernel<<<g, 256, SMEM2>>>(); }
    combine_kernel<<<NTOK, 256>>>(out);
}